// round 10
// baseline (speedup 1.0000x reference)
#include <cuda_runtime.h>
#include <cuda_fp16.h>
#include <cstdint>
#include <cstddef>

#define D 768
#define N_LAYERS 4
#define MAXN 50000
#define MAXE 100000

// ---------------- static scratch (allocation-free rule) ----------------
__device__ float  g_hA [(size_t)MAXN * D];
__device__ float  g_hB [(size_t)MAXN * D];
__device__ float  g_agg[(size_t)MAXN * D];
__device__ __align__(128) __half g_e16[(size_t)MAXE * D];  // edge features (fp16)
__device__ __align__(128) __half g_h16[(size_t)MAXN * D];  // fp16 mirror of h (gather source)
__device__ __align__(128) __half g_a16[(size_t)MAXE * D];  // GEMM-1 inputs (fp16)
__device__ __align__(128) __half g_t16[(size_t)MAXE * D];  // hidden activations (fp16)
__device__ __align__(128) __half g_w16[(size_t)12 * D * D]; // transposed fp16 weights [n][k]

// ---------------- tiny helpers ----------------
__device__ __forceinline__ float gelu_f(float x) {
    const float k0 = 0.7978845608028654f;
    const float k1 = 0.044715f;
    return 0.5f * x * (1.0f + tanhf(k0 * (x + k1 * x * x * x)));
}
template <int ACT>
__device__ __forceinline__ float actf(float x) {
    if (ACT == 1) return fmaxf(x, 0.0f);
    if (ACT == 2) return gelu_f(x);
    return x;
}
__device__ __forceinline__ void block_reduce2(float& s1, float& s2, float* shm) {
    #pragma unroll
    for (int o = 16; o > 0; o >>= 1) {
        s1 += __shfl_xor_sync(0xffffffffu, s1, o);
        s2 += __shfl_xor_sync(0xffffffffu, s2, o);
    }
    int wid = threadIdx.x >> 5, lane = threadIdx.x & 31;
    if (lane == 0) { shm[wid] = s1; shm[8 + wid] = s2; }
    __syncthreads();
    float a = 0.f, b = 0.f;
    #pragma unroll
    for (int i = 0; i < 8; i++) { a += shm[i]; b += shm[8 + i]; }
    s1 = a; s2 = b;
}

__device__ __forceinline__ void cp_async16(void* s, const void* g) {
    uint32_t sa = (uint32_t)__cvta_generic_to_shared(s);
    asm volatile("cp.async.cg.shared.global [%0], [%1], 16;" :: "r"(sa), "l"(g));
}
__device__ __forceinline__ void ldsm_x4(uint32_t* r, uint32_t addr) {
    asm volatile("ldmatrix.sync.aligned.m8n8.x4.shared.b16 {%0,%1,%2,%3}, [%4];"
                 : "=r"(r[0]), "=r"(r[1]), "=r"(r[2]), "=r"(r[3]) : "r"(addr));
}
__device__ __forceinline__ void mma_f16(float* c, const uint32_t* a, uint32_t b0, uint32_t b1) {
    asm volatile(
        "mma.sync.aligned.m16n8k16.row.col.f32.f16.f16.f32 "
        "{%0,%1,%2,%3},{%4,%5,%6,%7},{%8,%9},{%0,%1,%2,%3};"
        : "+f"(c[0]), "+f"(c[1]), "+f"(c[2]), "+f"(c[3])
        : "r"(a[0]), "r"(a[1]), "r"(a[2]), "r"(a[3]), "r"(b0), "r"(b1));
}

// ---------------- fp16 tensor-core GEMM (single-barrier multistage) ----------------
// C[M,768] = act(A[M,768] @ Wt^T + bias); A fp16 row-major, Wt fp16 [N][K] row-major.
// CTA tile 128(M) x 256(N), 512 threads (warps 4M x 4N, warp tile 32x64),
// BK=32 halves, 4-stage cp.async pipeline, ldmatrix operand loads.
#define BM 128
#define BN 256
#define BK 32
#define NT (D / BK)                      // 24
#define NSTAGE 4
#define SROW 80                          // smem row pitch bytes (40 halves) -> LDSM conflict-free
#define A_BYTES (BM * SROW)              // 10240
#define STAGE_BYTES (A_BYTES + BN * SROW)  // 30720
#define GEMM_THREADS 512
#define GEMM_SMEM (NSTAGE * STAGE_BYTES)   // 122880

template <int ACT, bool HOUT>
__global__ void __launch_bounds__(GEMM_THREADS, 1)
gemm_kernel(const __half* __restrict__ A, const __half* __restrict__ Wt,
            const float* __restrict__ bias, void* __restrict__ Cv, int M)
{
    extern __shared__ char smem[];
    const int t  = threadIdx.x;
    const int m0 = blockIdx.y * BM;
    const int n0 = blockIdx.x * BN;
    const uint32_t sbu = (uint32_t)__cvta_generic_to_shared(smem);

    auto load_stage = [&](int s, int kt) {
        char* abuf = smem + s * STAGE_BYTES;
        char* bbuf = abuf + A_BYTES;
        {   // A: 128 rows x 64B = 512 chunks, 1/thread
            int row = t >> 2, c = t & 3;
            int m = m0 + row; m = (m < M) ? m : (M - 1);
            cp_async16(abuf + row * SROW + c * 16, A + (size_t)m * D + kt * BK + c * 8);
        }
        #pragma unroll
        for (int i = 0; i < 2; i++) {   // B: 256 rows x 64B = 1024 chunks
            int q = t + i * GEMM_THREADS;
            int row = q >> 2, c = q & 3;
            cp_async16(bbuf + row * SROW + c * 16, Wt + (size_t)(n0 + row) * D + kt * BK + c * 8);
        }
    };

    float acc[2][8][4];
    #pragma unroll
    for (int i = 0; i < 2; i++)
        #pragma unroll
        for (int j = 0; j < 8; j++)
            #pragma unroll
            for (int k = 0; k < 4; k++) acc[i][j][k] = 0.f;

    #pragma unroll
    for (int s = 0; s < NSTAGE; s++) {
        load_stage(s, s);
        asm volatile("cp.async.commit_group;" ::: "memory");
    }

    const int lane = t & 31, wid = t >> 5;
    const int wm = (wid & 3) * 32;      // warp M offset (4 warps over 128)
    const int wn = (wid >> 2) * 64;     // warp N offset (4 warps over 256)
    const int gr = lane >> 2, tig = lane & 3;

    // per-thread ldmatrix row offsets (bytes within tile)
    const uint32_t a_off0 = (uint32_t)((wm + (lane & 15)) * SROW + (lane >> 4) * 16);
    const uint32_t b_off0 = (uint32_t)((wn + (lane & 7) + ((lane >> 4) & 1) * 8) * SROW
                                       + ((lane >> 3) & 1) * 16);

    for (int kt = 0; kt < NT; ++kt) {
        const int s = kt % NSTAGE;
        // stage kt's group completes exactly when <= NSTAGE-2 groups remain outstanding
        asm volatile("cp.async.wait_group %0;" :: "n"(NSTAGE - 2) : "memory");
        __syncthreads();
        // refill the stage consumed LAST iteration (all warps passed the barrier above,
        // so its consumers are done); issuing loads BEFORE compute overlaps LDGSTS with MMA
        {
            int ktn = kt + NSTAGE - 1;
            if (kt > 0 && ktn < NT) load_stage(ktn % NSTAGE, ktn);
            asm volatile("cp.async.commit_group;" ::: "memory");
        }
        const uint32_t sa = sbu + s * STAGE_BYTES;
        const uint32_t sb = sa + A_BYTES;
        #pragma unroll
        for (int kc = 0; kc < 2; kc++) {           // two k16 sub-tiles
            uint32_t af[2][4];
            #pragma unroll
            for (int mi = 0; mi < 2; mi++)
                ldsm_x4(af[mi], sa + a_off0 + mi * 16 * SROW + kc * 32);
            #pragma unroll
            for (int jp = 0; jp < 4; jp++) {       // pairs of n-tiles
                uint32_t bf[4];
                ldsm_x4(bf, sb + b_off0 + jp * 16 * SROW + kc * 32);
                mma_f16(acc[0][jp * 2 + 0], af[0], bf[0], bf[1]);
                mma_f16(acc[1][jp * 2 + 0], af[1], bf[0], bf[1]);
                mma_f16(acc[0][jp * 2 + 1], af[0], bf[2], bf[3]);
                mma_f16(acc[1][jp * 2 + 1], af[1], bf[2], bf[3]);
            }
        }
    }

    // epilogue: bias + activation + store (fp16 for hidden/edge, fp32 otherwise)
    #pragma unroll
    for (int mi = 0; mi < 2; mi++) {
        int row0 = m0 + wm + mi * 16 + gr;
        #pragma unroll
        for (int ni = 0; ni < 8; ni++) {
            int col = n0 + wn + ni * 8 + tig * 2;
            float bv0 = __ldg(bias + col), bv1 = __ldg(bias + col + 1);
            float v0 = actf<ACT>(acc[mi][ni][0] + bv0);
            float v1 = actf<ACT>(acc[mi][ni][1] + bv1);
            float v2 = actf<ACT>(acc[mi][ni][2] + bv0);
            float v3 = actf<ACT>(acc[mi][ni][3] + bv1);
            if (HOUT) {
                __half* C = (__half*)Cv;
                if (row0 < M)
                    *(__half2*)(C + (size_t)row0 * D + col) = __floats2half2_rn(v0, v1);
                if (row0 + 8 < M)
                    *(__half2*)(C + (size_t)(row0 + 8) * D + col) = __floats2half2_rn(v2, v3);
            } else {
                float* C = (float*)Cv;
                if (row0 < M)
                    *(float2*)(C + (size_t)row0 * D + col) = make_float2(v0, v1);
                if (row0 + 8 < M)
                    *(float2*)(C + (size_t)(row0 + 8) * D + col) = make_float2(v2, v3);
            }
        }
    }
}

// ---------------- weight transpose + fp16 convert, all 12 matrices in ONE launch ----------------
struct WPtrs { const float* p[6]; };   // atom_w1, atom_w2, bond_w1, bond_w2, conv_w1, conv_w2
__global__ void transpose_all_kernel(WPtrs w, __half* __restrict__ wt) {
    int mat = blockIdx.z;
    const float* W = (mat < 4) ? w.p[mat]
                   : (mat < 8) ? w.p[4] + (size_t)(mat - 4) * D * D
                               : w.p[5] + (size_t)(mat - 8) * D * D;
    __half* Wt = wt + (size_t)mat * D * D;
    __shared__ float tile[32][33];
    int bx = blockIdx.x * 32;   // n block
    int by = blockIdx.y * 32;   // k block
    int tx = threadIdx.x, ty = threadIdx.y;   // 32 x 8
    #pragma unroll
    for (int j = 0; j < 32; j += 8)
        tile[ty + j][tx] = W[(size_t)(by + ty + j) * D + bx + tx];   // tile[k][n]
    __syncthreads();
    #pragma unroll
    for (int j = 0; j < 32; j += 8)
        Wt[(size_t)(bx + ty + j) * D + by + tx] = __float2half_rn(tile[tx][ty + j]);
}

// ---------------- fp32 -> fp16 convert (agg before conv GEMM) ----------------
__global__ void cvt_half_kernel(const float4* __restrict__ src, __half2* __restrict__ dst, int n4) {
    int i = blockIdx.x * blockDim.x + threadIdx.x;
    if (i < n4) {
        float4 v = src[i];
        dst[i * 2 + 0] = __floats2half2_rn(v.x, v.y);
        dst[i * 2 + 1] = __floats2half2_rn(v.z, v.w);
    }
}

// ---------------- seed: agg = h (fp32) and h16 = fp16(h), one pass ----------------
__global__ void seed_kernel(const float4* __restrict__ h, float4* __restrict__ agg,
                            __half2* __restrict__ h16, int n4) {
    int i = blockIdx.x * blockDim.x + threadIdx.x;
    if (i < n4) {
        float4 v = h[i];
        agg[i] = v;
        h16[i * 2 + 0] = __floats2half2_rn(v.x, v.y);
        h16[i * 2 + 1] = __floats2half2_rn(v.z, v.w);
    }
}

// ---------------- embedding sum + LayerNorm (fp16 output for GEMM) ----------------
__global__ void embed_ln_kernel(const int* __restrict__ ids,
                                const float* __restrict__ emb,
                                const float* __restrict__ g,
                                const float* __restrict__ bta,
                                __half* __restrict__ out,
                                int F, int V) {
    int n = blockIdx.x;
    int t = threadIdx.x;
    __shared__ int   sid[16];
    __shared__ float shm[16];
    if (t < F) sid[t] = ids[(size_t)n * F + t];
    __syncthreads();

    float x[3];
    #pragma unroll
    for (int j = 0; j < 3; j++) {
        int d = t + j * 256;
        float s = 0.f;
        for (int f = 0; f < F; f++)
            s += emb[((size_t)(f * V + sid[f])) * D + d];
        x[j] = s;
    }
    float s1 = x[0] + x[1] + x[2];
    float s2 = x[0]*x[0] + x[1]*x[1] + x[2]*x[2];
    block_reduce2(s1, s2, shm);
    float mean = s1 * (1.0f / D);
    float var  = s2 * (1.0f / D) - mean * mean;
    float inv  = rsqrtf(var + 1e-5f);
    __half* o = out + (size_t)n * D;
    #pragma unroll
    for (int j = 0; j < 3; j++) {
        int d = t + j * 256;
        o[d] = __float2half_rn((x[j] - mean) * inv * g[d] + bta[d]);
    }
}

// ---------------- edge message: agg[dst] += relu(h16[src] + e16) ----------------
__global__ void edge_msg_kernel(const int* __restrict__ ei,
                                const __half* __restrict__ h,
                                const __half* __restrict__ e,
                                float* __restrict__ agg, int E) {
    int eid = blockIdx.x;
    int src = __ldg(ei + eid);
    int dst = __ldg(ei + E + eid);
    int t = threadIdx.x;  // 192 threads * 4 halves = 768
    const __half2* hp = (const __half2*)(h + (size_t)src * D) + t * 2;
    const __half2* ep = (const __half2*)(e + (size_t)eid * D) + t * 2;
    float2 h0 = __half22float2(hp[0]);
    float2 h1 = __half22float2(hp[1]);
    float2 e0 = __half22float2(ep[0]);
    float2 e1 = __half22float2(ep[1]);
    float* a = agg + (size_t)dst * D + t * 4;
    atomicAdd(a + 0, fmaxf(h0.x + e0.x, 0.f));
    atomicAdd(a + 1, fmaxf(h0.y + e0.y, 0.f));
    atomicAdd(a + 2, fmaxf(h1.x + e1.x, 0.f));
    atomicAdd(a + 3, fmaxf(h1.y + e1.y, 0.f));
}

// ---------------- fused gelu + residual + LayerNorm (+ agg seed + h16 mirror) ----------------
__global__ void ln_res_kernel(const float* __restrict__ z,
                              const float* __restrict__ hin,
                              const float* __restrict__ g,
                              const float* __restrict__ bta,
                              float* __restrict__ out,
                              float* __restrict__ aggc,
                              __half* __restrict__ h16) {
    int n = blockIdx.x;
    int t = threadIdx.x;
    __shared__ float shm[16];
    float x[3];
    #pragma unroll
    for (int j = 0; j < 3; j++) {
        int d = t + j * 256;
        x[j] = gelu_f(z[(size_t)n * D + d]) + hin[(size_t)n * D + d];
    }
    float s1 = x[0] + x[1] + x[2];
    float s2 = x[0]*x[0] + x[1]*x[1] + x[2]*x[2];
    block_reduce2(s1, s2, shm);
    float mean = s1 * (1.0f / D);
    float var  = s2 * (1.0f / D) - mean * mean;
    float inv  = rsqrtf(var + 1e-5f);
    #pragma unroll
    for (int j = 0; j < 3; j++) {
        int d = t + j * 256;
        float r = (x[j] - mean) * inv * g[d] + bta[d];
        out[(size_t)n * D + d] = r;
        if (aggc) {
            aggc[(size_t)n * D + d] = r;
            h16[(size_t)n * D + d] = __float2half_rn(r);
        }
    }
}

// ---------------- host orchestration ----------------
extern "C" void kernel_launch(void* const* d_in, const int* in_sizes, int n_in,
                              void* d_out, int out_size) {
    const int*   x          = (const int*)d_in[0];
    const int*   edge_attr  = (const int*)d_in[1];
    const int*   edge_index = (const int*)d_in[2];
    const float* atom_emb   = (const float*)d_in[3];
    const float* atom_ln_g  = (const float*)d_in[4];
    const float* atom_ln_b  = (const float*)d_in[5];
    const float* atom_w1    = (const float*)d_in[6];
    const float* atom_b1    = (const float*)d_in[7];
    const float* atom_w2    = (const float*)d_in[8];
    const float* atom_b2    = (const float*)d_in[9];
    const float* bond_emb   = (const float*)d_in[10];
    const float* bond_ln_g  = (const float*)d_in[11];
    const float* bond_ln_b  = (const float*)d_in[12];
    const float* bond_w1    = (const float*)d_in[13];
    const float* bond_b1    = (const float*)d_in[14];
    const float* bond_w2    = (const float*)d_in[15];
    const float* bond_b2    = (const float*)d_in[16];
    const float* conv_w1    = (const float*)d_in[17];
    const float* conv_b1    = (const float*)d_in[18];
    const float* conv_w2    = (const float*)d_in[19];
    const float* conv_b2    = (const float*)d_in[20];
    const float* ln_g       = (const float*)d_in[21];
    const float* ln_b       = (const float*)d_in[22];
    float* out = (float*)d_out;

    int N = in_sizes[0] / 9;
    int E = in_sizes[1] / 3;
    if (N > MAXN) N = MAXN;
    if (E > MAXE) E = MAXE;

    float *phA, *phB, *pagg;
    __half *pe16, *ph16, *pa16, *pt16, *pw16;
    cudaGetSymbolAddress((void**)&phA,  g_hA);
    cudaGetSymbolAddress((void**)&phB,  g_hB);
    cudaGetSymbolAddress((void**)&pagg, g_agg);
    cudaGetSymbolAddress((void**)&pe16, g_e16);
    cudaGetSymbolAddress((void**)&ph16, g_h16);
    cudaGetSymbolAddress((void**)&pa16, g_a16);
    cudaGetSymbolAddress((void**)&pt16, g_t16);
    cudaGetSymbolAddress((void**)&pw16, g_w16);

    cudaFuncSetAttribute(gemm_kernel<0, false>, cudaFuncAttributeMaxDynamicSharedMemorySize, GEMM_SMEM);
    cudaFuncSetAttribute(gemm_kernel<0, true>,  cudaFuncAttributeMaxDynamicSharedMemorySize, GEMM_SMEM);
    cudaFuncSetAttribute(gemm_kernel<1, true>,  cudaFuncAttributeMaxDynamicSharedMemorySize, GEMM_SMEM);
    cudaFuncSetAttribute(gemm_kernel<2, true>,  cudaFuncAttributeMaxDynamicSharedMemorySize, GEMM_SMEM);

    // ---- launch 0: transpose + fp16-convert all 12 weight matrices ----
    WPtrs wp;
    wp.p[0] = atom_w1; wp.p[1] = atom_w2; wp.p[2] = bond_w1;
    wp.p[3] = bond_w2; wp.p[4] = conv_w1; wp.p[5] = conv_w2;
    transpose_all_kernel<<<dim3(D / 32, D / 32, 12), dim3(32, 8)>>>(wp, pw16);

    auto WT = [&](int i) { return pw16 + (size_t)i * D * D; };
    dim3 gN(D / BN, (N + BM - 1) / BM);
    dim3 gE(D / BN, (E + BM - 1) / BM);

    // ---- atom encode: h = enc(x) ----
    embed_ln_kernel<<<N, 256>>>(x, atom_emb, atom_ln_g, atom_ln_b, pa16, 9, 128);
    gemm_kernel<2, true ><<<gN, GEMM_THREADS, GEMM_SMEM>>>(pa16, WT(0), atom_b1, pt16, N);
    gemm_kernel<0, false><<<gN, GEMM_THREADS, GEMM_SMEM>>>(pt16, WT(1), atom_b2, phA, N);

    // ---- bond encode: e16 = enc(edge_attr), kept fp16 ----
    embed_ln_kernel<<<E, 256>>>(edge_attr, bond_emb, bond_ln_g, bond_ln_b, pa16, 3, 8);
    gemm_kernel<2, true ><<<gE, GEMM_THREADS, GEMM_SMEM>>>(pa16, WT(2), bond_b1, pt16, E);  // launch #5 -> ncu
    gemm_kernel<0, true ><<<gE, GEMM_THREADS, GEMM_SMEM>>>(pt16, WT(3), bond_b2, pe16, E);

    // ---- layer 0 seeds: agg = h, h16 = fp16(h) ----
    int n4 = N * D / 4;
    seed_kernel<<<(n4 + 255) / 256, 256>>>((const float4*)phA, (float4*)pagg, (__half2*)ph16, n4);

    const float* hcur = phA;
    float* hnext = phB;
    for (int l = 0; l < N_LAYERS; l++) {
        // agg += relu(h16[src] + e16)   (agg pre-seeded with h -> z = h + sum msg)
        edge_msg_kernel<<<E, 192>>>(edge_index, ph16, pe16, pagg, E);
        // convert z (=agg) to fp16 for the conv GEMM
        cvt_half_kernel<<<(n4 + 255) / 256, 256>>>((const float4*)pagg, (__half2*)pa16, n4);
        // conv MLP
        gemm_kernel<1, true ><<<gN, GEMM_THREADS, GEMM_SMEM>>>(pa16, WT(4 + l), conv_b1 + l * D, pt16, N);
        gemm_kernel<0, false><<<gN, GEMM_THREADS, GEMM_SMEM>>>(pt16, WT(8 + l), conv_b2 + l * D, pagg, N);
        // h = LN(gelu(z) + h_in); also seed next layer's agg and refresh h16 mirror
        float* dst  = (l == N_LAYERS - 1) ? out : hnext;
        float* aggc = (l == N_LAYERS - 1) ? nullptr : pagg;
        ln_res_kernel<<<N, 256>>>(pagg, hcur, ln_g + l * D, ln_b + l * D, dst, aggc, ph16);

        float* old = (float*)hcur;
        hcur = dst;
        hnext = old;
    }
}

// round 11
// speedup vs baseline: 1.0753x; 1.0753x over previous
#include <cuda_runtime.h>
#include <cuda_fp16.h>
#include <cstdint>
#include <cstddef>

#define D 768
#define N_LAYERS 4
#define MAXN 50000
#define MAXE 100000

// ---------------- static scratch (allocation-free rule) ----------------
__device__ float  g_hA [(size_t)MAXN * D];
__device__ float  g_hB [(size_t)MAXN * D];
__device__ float  g_agg[(size_t)MAXN * D];
__device__ __align__(128) __half g_e16[(size_t)MAXE * D];  // edge features (fp16)
__device__ __align__(128) __half g_h16[(size_t)MAXN * D];  // fp16 mirror of h (gather source)
__device__ __align__(128) __half g_a16[(size_t)MAXE * D];  // GEMM-1 inputs (fp16)
__device__ __align__(128) __half g_t16[(size_t)MAXE * D];  // hidden activations (fp16)
__device__ __align__(128) __half g_w16[(size_t)12 * D * D]; // transposed fp16 weights [n][k]

// ---------------- tiny helpers ----------------
__device__ __forceinline__ float gelu_f(float x) {
    const float k0 = 0.7978845608028654f;
    const float k1 = 0.044715f;
    return 0.5f * x * (1.0f + tanhf(k0 * (x + k1 * x * x * x)));
}
template <int ACT>
__device__ __forceinline__ float actf(float x) {
    if (ACT == 1) return fmaxf(x, 0.0f);
    if (ACT == 2) return gelu_f(x);
    return x;
}
__device__ __forceinline__ void block_reduce2(float& s1, float& s2, float* shm) {
    #pragma unroll
    for (int o = 16; o > 0; o >>= 1) {
        s1 += __shfl_xor_sync(0xffffffffu, s1, o);
        s2 += __shfl_xor_sync(0xffffffffu, s2, o);
    }
    int wid = threadIdx.x >> 5, lane = threadIdx.x & 31;
    if (lane == 0) { shm[wid] = s1; shm[8 + wid] = s2; }
    __syncthreads();
    float a = 0.f, b = 0.f;
    #pragma unroll
    for (int i = 0; i < 8; i++) { a += shm[i]; b += shm[8 + i]; }
    s1 = a; s2 = b;
}

__device__ __forceinline__ void cp_async16(void* s, const void* g) {
    uint32_t sa = (uint32_t)__cvta_generic_to_shared(s);
    asm volatile("cp.async.cg.shared.global [%0], [%1], 16;" :: "r"(sa), "l"(g));
}
__device__ __forceinline__ void ldsm_x4(uint32_t* r, uint32_t addr) {
    asm volatile("ldmatrix.sync.aligned.m8n8.x4.shared.b16 {%0,%1,%2,%3}, [%4];"
                 : "=r"(r[0]), "=r"(r[1]), "=r"(r[2]), "=r"(r[3]) : "r"(addr));
}
__device__ __forceinline__ void mma_f16(float* c, const uint32_t* a, uint32_t b0, uint32_t b1) {
    asm volatile(
        "mma.sync.aligned.m16n8k16.row.col.f32.f16.f16.f32 "
        "{%0,%1,%2,%3},{%4,%5,%6,%7},{%8,%9},{%0,%1,%2,%3};"
        : "+f"(c[0]), "+f"(c[1]), "+f"(c[2]), "+f"(c[3])
        : "r"(a[0]), "r"(a[1]), "r"(a[2]), "r"(a[3]), "r"(b0), "r"(b1));
}

// ---------------- fp16 tensor-core GEMM (2 CTAs/SM) ----------------
// C[M,768] = act(A[M,768] @ Wt^T + bias); A fp16 row-major, Wt fp16 [N][K] row-major.
// CTA tile 128(M) x 128(N), 256 threads (warps 4M x 2N, warp tile 32x64),
// BK=32 halves, 4-stage cp.async pipeline, ldmatrix operand loads.
// 80 KB smem + <=128 regs -> 2 CTAs resident per SM (cross-CTA bubble hiding).
#define BM 128
#define BN 128
#define BK 32
#define NT (D / BK)                      // 24
#define NSTAGE 4
#define SROW 80                          // smem row pitch bytes (40 halves) -> LDSM conflict-free
#define A_BYTES (BM * SROW)              // 10240
#define STAGE_BYTES (A_BYTES + BN * SROW)  // 20480
#define GEMM_THREADS 256
#define GEMM_SMEM (NSTAGE * STAGE_BYTES)   // 81920

template <int ACT, bool HOUT>
__global__ void __launch_bounds__(GEMM_THREADS, 2)
gemm_kernel(const __half* __restrict__ A, const __half* __restrict__ Wt,
            const float* __restrict__ bias, void* __restrict__ Cv, int M)
{
    extern __shared__ char smem[];
    const int t  = threadIdx.x;
    const int m0 = blockIdx.y * BM;
    const int n0 = blockIdx.x * BN;
    const uint32_t sbu = (uint32_t)__cvta_generic_to_shared(smem);

    auto load_stage = [&](int s, int kt) {
        char* abuf = smem + s * STAGE_BYTES;
        char* bbuf = abuf + A_BYTES;
        #pragma unroll
        for (int i = 0; i < 2; i++) {   // A: 128 rows x 64B = 512 chunks
            int q = t + i * GEMM_THREADS;
            int row = q >> 2, c = q & 3;
            int m = m0 + row; m = (m < M) ? m : (M - 1);
            cp_async16(abuf + row * SROW + c * 16, A + (size_t)m * D + kt * BK + c * 8);
        }
        #pragma unroll
        for (int i = 0; i < 2; i++) {   // B: 128 rows x 64B = 512 chunks
            int q = t + i * GEMM_THREADS;
            int row = q >> 2, c = q & 3;
            cp_async16(bbuf + row * SROW + c * 16, Wt + (size_t)(n0 + row) * D + kt * BK + c * 8);
        }
    };

    float acc[2][8][4];
    #pragma unroll
    for (int i = 0; i < 2; i++)
        #pragma unroll
        for (int j = 0; j < 8; j++)
            #pragma unroll
            for (int k = 0; k < 4; k++) acc[i][j][k] = 0.f;

    #pragma unroll
    for (int s = 0; s < NSTAGE; s++) {
        load_stage(s, s);
        asm volatile("cp.async.commit_group;" ::: "memory");
    }

    const int lane = t & 31, wid = t >> 5;
    const int wm = (wid & 3) * 32;      // warp M offset (4 warps over 128)
    const int wn = (wid >> 2) * 64;     // warp N offset (2 warps over 128)
    const int gr = lane >> 2, tig = lane & 3;

    // per-thread ldmatrix row offsets (bytes within tile)
    const uint32_t a_off0 = (uint32_t)((wm + (lane & 15)) * SROW + (lane >> 4) * 16);
    const uint32_t b_off0 = (uint32_t)((wn + (lane & 7) + ((lane >> 4) & 1) * 8) * SROW
                                       + ((lane >> 3) & 1) * 16);

    for (int kt = 0; kt < NT; ++kt) {
        const int s = kt % NSTAGE;
        asm volatile("cp.async.wait_group %0;" :: "n"(NSTAGE - 1) : "memory");
        __syncthreads();
        const uint32_t sa = sbu + s * STAGE_BYTES;
        const uint32_t sb = sa + A_BYTES;
        #pragma unroll
        for (int kc = 0; kc < 2; kc++) {           // two k16 sub-tiles
            uint32_t af[2][4];
            #pragma unroll
            for (int mi = 0; mi < 2; mi++)
                ldsm_x4(af[mi], sa + a_off0 + mi * 16 * SROW + kc * 32);
            #pragma unroll
            for (int jp = 0; jp < 4; jp++) {       // pairs of n-tiles
                uint32_t bf[4];
                ldsm_x4(bf, sb + b_off0 + jp * 16 * SROW + kc * 32);
                mma_f16(acc[0][jp * 2 + 0], af[0], bf[0], bf[1]);
                mma_f16(acc[1][jp * 2 + 0], af[1], bf[0], bf[1]);
                mma_f16(acc[0][jp * 2 + 1], af[0], bf[2], bf[3]);
                mma_f16(acc[1][jp * 2 + 1], af[1], bf[2], bf[3]);
            }
        }
        __syncthreads();                 // stage fully consumed before refill
        if (kt + NSTAGE < NT) load_stage(s, kt + NSTAGE);
        asm volatile("cp.async.commit_group;" ::: "memory");
    }

    // epilogue: bias + activation + store (fp16 for hidden/edge, fp32 otherwise)
    #pragma unroll
    for (int mi = 0; mi < 2; mi++) {
        int row0 = m0 + wm + mi * 16 + gr;
        #pragma unroll
        for (int ni = 0; ni < 8; ni++) {
            int col = n0 + wn + ni * 8 + tig * 2;
            float bv0 = __ldg(bias + col), bv1 = __ldg(bias + col + 1);
            float v0 = actf<ACT>(acc[mi][ni][0] + bv0);
            float v1 = actf<ACT>(acc[mi][ni][1] + bv1);
            float v2 = actf<ACT>(acc[mi][ni][2] + bv0);
            float v3 = actf<ACT>(acc[mi][ni][3] + bv1);
            if (HOUT) {
                __half* C = (__half*)Cv;
                if (row0 < M)
                    *(__half2*)(C + (size_t)row0 * D + col) = __floats2half2_rn(v0, v1);
                if (row0 + 8 < M)
                    *(__half2*)(C + (size_t)(row0 + 8) * D + col) = __floats2half2_rn(v2, v3);
            } else {
                float* C = (float*)Cv;
                if (row0 < M)
                    *(float2*)(C + (size_t)row0 * D + col) = make_float2(v0, v1);
                if (row0 + 8 < M)
                    *(float2*)(C + (size_t)(row0 + 8) * D + col) = make_float2(v2, v3);
            }
        }
    }
}

// ---------------- weight transpose + fp16 convert, all 12 matrices in ONE launch ----------------
struct WPtrs { const float* p[6]; };   // atom_w1, atom_w2, bond_w1, bond_w2, conv_w1, conv_w2
__global__ void transpose_all_kernel(WPtrs w, __half* __restrict__ wt) {
    int mat = blockIdx.z;
    const float* W = (mat < 4) ? w.p[mat]
                   : (mat < 8) ? w.p[4] + (size_t)(mat - 4) * D * D
                               : w.p[5] + (size_t)(mat - 8) * D * D;
    __half* Wt = wt + (size_t)mat * D * D;
    __shared__ float tile[32][33];
    int bx = blockIdx.x * 32;   // n block
    int by = blockIdx.y * 32;   // k block
    int tx = threadIdx.x, ty = threadIdx.y;   // 32 x 8
    #pragma unroll
    for (int j = 0; j < 32; j += 8)
        tile[ty + j][tx] = W[(size_t)(by + ty + j) * D + bx + tx];   // tile[k][n]
    __syncthreads();
    #pragma unroll
    for (int j = 0; j < 32; j += 8)
        Wt[(size_t)(bx + ty + j) * D + by + tx] = __float2half_rn(tile[tx][ty + j]);
}

// ---------------- fp32 -> fp16 convert (agg before conv GEMM) ----------------
__global__ void cvt_half_kernel(const float4* __restrict__ src, __half2* __restrict__ dst, int n4) {
    int i = blockIdx.x * blockDim.x + threadIdx.x;
    if (i < n4) {
        float4 v = src[i];
        dst[i * 2 + 0] = __floats2half2_rn(v.x, v.y);
        dst[i * 2 + 1] = __floats2half2_rn(v.z, v.w);
    }
}

// ---------------- seed: agg = h (fp32) and h16 = fp16(h), one pass ----------------
__global__ void seed_kernel(const float4* __restrict__ h, float4* __restrict__ agg,
                            __half2* __restrict__ h16, int n4) {
    int i = blockIdx.x * blockDim.x + threadIdx.x;
    if (i < n4) {
        float4 v = h[i];
        agg[i] = v;
        h16[i * 2 + 0] = __floats2half2_rn(v.x, v.y);
        h16[i * 2 + 1] = __floats2half2_rn(v.z, v.w);
    }
}

// ---------------- embedding sum + LayerNorm (fp16 output for GEMM) ----------------
__global__ void embed_ln_kernel(const int* __restrict__ ids,
                                const float* __restrict__ emb,
                                const float* __restrict__ g,
                                const float* __restrict__ bta,
                                __half* __restrict__ out,
                                int F, int V) {
    int n = blockIdx.x;
    int t = threadIdx.x;
    __shared__ int   sid[16];
    __shared__ float shm[16];
    if (t < F) sid[t] = ids[(size_t)n * F + t];
    __syncthreads();

    float x[3];
    #pragma unroll
    for (int j = 0; j < 3; j++) {
        int d = t + j * 256;
        float s = 0.f;
        for (int f = 0; f < F; f++)
            s += emb[((size_t)(f * V + sid[f])) * D + d];
        x[j] = s;
    }
    float s1 = x[0] + x[1] + x[2];
    float s2 = x[0]*x[0] + x[1]*x[1] + x[2]*x[2];
    block_reduce2(s1, s2, shm);
    float mean = s1 * (1.0f / D);
    float var  = s2 * (1.0f / D) - mean * mean;
    float inv  = rsqrtf(var + 1e-5f);
    __half* o = out + (size_t)n * D;
    #pragma unroll
    for (int j = 0; j < 3; j++) {
        int d = t + j * 256;
        o[d] = __float2half_rn((x[j] - mean) * inv * g[d] + bta[d]);
    }
}

// ---------------- edge message: agg[dst] += relu(h16[src] + e16) ----------------
__global__ void edge_msg_kernel(const int* __restrict__ ei,
                                const __half* __restrict__ h,
                                const __half* __restrict__ e,
                                float* __restrict__ agg, int E) {
    int eid = blockIdx.x;
    int src = __ldg(ei + eid);
    int dst = __ldg(ei + E + eid);
    int t = threadIdx.x;  // 192 threads * 4 halves = 768
    const __half2* hp = (const __half2*)(h + (size_t)src * D) + t * 2;
    const __half2* ep = (const __half2*)(e + (size_t)eid * D) + t * 2;
    float2 h0 = __half22float2(hp[0]);
    float2 h1 = __half22float2(hp[1]);
    float2 e0 = __half22float2(ep[0]);
    float2 e1 = __half22float2(ep[1]);
    float* a = agg + (size_t)dst * D + t * 4;
    atomicAdd(a + 0, fmaxf(h0.x + e0.x, 0.f));
    atomicAdd(a + 1, fmaxf(h0.y + e0.y, 0.f));
    atomicAdd(a + 2, fmaxf(h1.x + e1.x, 0.f));
    atomicAdd(a + 3, fmaxf(h1.y + e1.y, 0.f));
}

// ---------------- fused gelu + residual + LayerNorm (+ agg seed + h16 mirror) ----------------
__global__ void ln_res_kernel(const float* __restrict__ z,
                              const float* __restrict__ hin,
                              const float* __restrict__ g,
                              const float* __restrict__ bta,
                              float* __restrict__ out,
                              float* __restrict__ aggc,
                              __half* __restrict__ h16) {
    int n = blockIdx.x;
    int t = threadIdx.x;
    __shared__ float shm[16];
    float x[3];
    #pragma unroll
    for (int j = 0; j < 3; j++) {
        int d = t + j * 256;
        x[j] = gelu_f(z[(size_t)n * D + d]) + hin[(size_t)n * D + d];
    }
    float s1 = x[0] + x[1] + x[2];
    float s2 = x[0]*x[0] + x[1]*x[1] + x[2]*x[2];
    block_reduce2(s1, s2, shm);
    float mean = s1 * (1.0f / D);
    float var  = s2 * (1.0f / D) - mean * mean;
    float inv  = rsqrtf(var + 1e-5f);
    #pragma unroll
    for (int j = 0; j < 3; j++) {
        int d = t + j * 256;
        float r = (x[j] - mean) * inv * g[d] + bta[d];
        out[(size_t)n * D + d] = r;
        if (aggc) {
            aggc[(size_t)n * D + d] = r;
            h16[(size_t)n * D + d] = __float2half_rn(r);
        }
    }
}

// ---------------- host orchestration ----------------
extern "C" void kernel_launch(void* const* d_in, const int* in_sizes, int n_in,
                              void* d_out, int out_size) {
    const int*   x          = (const int*)d_in[0];
    const int*   edge_attr  = (const int*)d_in[1];
    const int*   edge_index = (const int*)d_in[2];
    const float* atom_emb   = (const float*)d_in[3];
    const float* atom_ln_g  = (const float*)d_in[4];
    const float* atom_ln_b  = (const float*)d_in[5];
    const float* atom_w1    = (const float*)d_in[6];
    const float* atom_b1    = (const float*)d_in[7];
    const float* atom_w2    = (const float*)d_in[8];
    const float* atom_b2    = (const float*)d_in[9];
    const float* bond_emb   = (const float*)d_in[10];
    const float* bond_ln_g  = (const float*)d_in[11];
    const float* bond_ln_b  = (const float*)d_in[12];
    const float* bond_w1    = (const float*)d_in[13];
    const float* bond_b1    = (const float*)d_in[14];
    const float* bond_w2    = (const float*)d_in[15];
    const float* bond_b2    = (const float*)d_in[16];
    const float* conv_w1    = (const float*)d_in[17];
    const float* conv_b1    = (const float*)d_in[18];
    const float* conv_w2    = (const float*)d_in[19];
    const float* conv_b2    = (const float*)d_in[20];
    const float* ln_g       = (const float*)d_in[21];
    const float* ln_b       = (const float*)d_in[22];
    float* out = (float*)d_out;

    int N = in_sizes[0] / 9;
    int E = in_sizes[1] / 3;
    if (N > MAXN) N = MAXN;
    if (E > MAXE) E = MAXE;

    float *phA, *phB, *pagg;
    __half *pe16, *ph16, *pa16, *pt16, *pw16;
    cudaGetSymbolAddress((void**)&phA,  g_hA);
    cudaGetSymbolAddress((void**)&phB,  g_hB);
    cudaGetSymbolAddress((void**)&pagg, g_agg);
    cudaGetSymbolAddress((void**)&pe16, g_e16);
    cudaGetSymbolAddress((void**)&ph16, g_h16);
    cudaGetSymbolAddress((void**)&pa16, g_a16);
    cudaGetSymbolAddress((void**)&pt16, g_t16);
    cudaGetSymbolAddress((void**)&pw16, g_w16);

    cudaFuncSetAttribute(gemm_kernel<0, false>, cudaFuncAttributeMaxDynamicSharedMemorySize, GEMM_SMEM);
    cudaFuncSetAttribute(gemm_kernel<0, true>,  cudaFuncAttributeMaxDynamicSharedMemorySize, GEMM_SMEM);
    cudaFuncSetAttribute(gemm_kernel<1, true>,  cudaFuncAttributeMaxDynamicSharedMemorySize, GEMM_SMEM);
    cudaFuncSetAttribute(gemm_kernel<2, true>,  cudaFuncAttributeMaxDynamicSharedMemorySize, GEMM_SMEM);

    // ---- launch 0: transpose + fp16-convert all 12 weight matrices ----
    WPtrs wp;
    wp.p[0] = atom_w1; wp.p[1] = atom_w2; wp.p[2] = bond_w1;
    wp.p[3] = bond_w2; wp.p[4] = conv_w1; wp.p[5] = conv_w2;
    transpose_all_kernel<<<dim3(D / 32, D / 32, 12), dim3(32, 8)>>>(wp, pw16);

    auto WT = [&](int i) { return pw16 + (size_t)i * D * D; };
    dim3 gN(D / BN, (N + BM - 1) / BM);
    dim3 gE(D / BN, (E + BM - 1) / BM);

    // ---- atom encode: h = enc(x) ----
    embed_ln_kernel<<<N, 256>>>(x, atom_emb, atom_ln_g, atom_ln_b, pa16, 9, 128);
    gemm_kernel<2, true ><<<gN, GEMM_THREADS, GEMM_SMEM>>>(pa16, WT(0), atom_b1, pt16, N);
    gemm_kernel<0, false><<<gN, GEMM_THREADS, GEMM_SMEM>>>(pt16, WT(1), atom_b2, phA, N);

    // ---- bond encode: e16 = enc(edge_attr), kept fp16 ----
    embed_ln_kernel<<<E, 256>>>(edge_attr, bond_emb, bond_ln_g, bond_ln_b, pa16, 3, 8);
    gemm_kernel<2, true ><<<gE, GEMM_THREADS, GEMM_SMEM>>>(pa16, WT(2), bond_b1, pt16, E);  // launch #5 -> ncu
    gemm_kernel<0, true ><<<gE, GEMM_THREADS, GEMM_SMEM>>>(pt16, WT(3), bond_b2, pe16, E);

    // ---- layer 0 seeds: agg = h, h16 = fp16(h) ----
    int n4 = N * D / 4;
    seed_kernel<<<(n4 + 255) / 256, 256>>>((const float4*)phA, (float4*)pagg, (__half2*)ph16, n4);

    const float* hcur = phA;
    float* hnext = phB;
    for (int l = 0; l < N_LAYERS; l++) {
        // agg += relu(h16[src] + e16)   (agg pre-seeded with h -> z = h + sum msg)
        edge_msg_kernel<<<E, 192>>>(edge_index, ph16, pe16, pagg, E);
        // convert z (=agg) to fp16 for the conv GEMM
        cvt_half_kernel<<<(n4 + 255) / 256, 256>>>((const float4*)pagg, (__half2*)pa16, n4);
        // conv MLP
        gemm_kernel<1, true ><<<gN, GEMM_THREADS, GEMM_SMEM>>>(pa16, WT(4 + l), conv_b1 + l * D, pt16, N);
        gemm_kernel<0, false><<<gN, GEMM_THREADS, GEMM_SMEM>>>(pt16, WT(8 + l), conv_b2 + l * D, pagg, N);
        // h = LN(gelu(z) + h_in); also seed next layer's agg and refresh h16 mirror
        float* dst  = (l == N_LAYERS - 1) ? out : hnext;
        float* aggc = (l == N_LAYERS - 1) ? nullptr : pagg;
        ln_res_kernel<<<N, 256>>>(pagg, hcur, ln_g + l * D, ln_b + l * D, dst, aggc, ph16);

        float* old = (float*)hcur;
        hcur = dst;
        hnext = old;
    }
}

// round 12
// speedup vs baseline: 1.1737x; 1.0914x over previous
#include <cuda_runtime.h>
#include <cuda_fp16.h>
#include <cstdint>
#include <cstddef>

#define D 768
#define N_LAYERS 4
#define MAXN 50000
#define MAXE 100000

// ---------------- static scratch (allocation-free rule) ----------------
__device__ float  g_hA [(size_t)MAXN * D];
__device__ float  g_hB [(size_t)MAXN * D];
__device__ float  g_agg[(size_t)MAXN * D];
__device__ __align__(128) __half g_e16[(size_t)MAXE * D];  // edge features (fp16)
__device__ __align__(128) __half g_h16[(size_t)MAXN * D];  // fp16 mirror of h (gather source)
__device__ __align__(128) __half g_a16[(size_t)MAXE * D];  // GEMM-1 inputs (fp16)
__device__ __align__(128) __half g_t16[(size_t)MAXE * D];  // hidden activations (fp16)
__device__ __align__(128) __half g_w16[(size_t)12 * D * D]; // transposed fp16 weights [n][k]

// ---------------- tiny helpers ----------------
__device__ __forceinline__ float gelu_f(float x) {
    const float k0 = 0.7978845608028654f;
    const float k1 = 0.044715f;
    return 0.5f * x * (1.0f + tanhf(k0 * (x + k1 * x * x * x)));
}
template <int ACT>
__device__ __forceinline__ float actf(float x) {
    if (ACT == 1) return fmaxf(x, 0.0f);
    if (ACT == 2) return gelu_f(x);
    return x;
}
__device__ __forceinline__ void block_reduce2(float& s1, float& s2, float* shm) {
    #pragma unroll
    for (int o = 16; o > 0; o >>= 1) {
        s1 += __shfl_xor_sync(0xffffffffu, s1, o);
        s2 += __shfl_xor_sync(0xffffffffu, s2, o);
    }
    int wid = threadIdx.x >> 5, lane = threadIdx.x & 31;
    if (lane == 0) { shm[wid] = s1; shm[8 + wid] = s2; }
    __syncthreads();
    float a = 0.f, b = 0.f;
    #pragma unroll
    for (int i = 0; i < 8; i++) { a += shm[i]; b += shm[8 + i]; }
    s1 = a; s2 = b;
}

__device__ __forceinline__ void cp_async16(void* s, const void* g) {
    uint32_t sa = (uint32_t)__cvta_generic_to_shared(s);
    asm volatile("cp.async.cg.shared.global [%0], [%1], 16;" :: "r"(sa), "l"(g));
}
__device__ __forceinline__ void ldsm_x4(uint32_t* r, uint32_t addr) {
    asm volatile("ldmatrix.sync.aligned.m8n8.x4.shared.b16 {%0,%1,%2,%3}, [%4];"
                 : "=r"(r[0]), "=r"(r[1]), "=r"(r[2]), "=r"(r[3]) : "r"(addr));
}
__device__ __forceinline__ void mma_f16(float* c, const uint32_t* a, uint32_t b0, uint32_t b1) {
    asm volatile(
        "mma.sync.aligned.m16n8k16.row.col.f32.f16.f16.f32 "
        "{%0,%1,%2,%3},{%4,%5,%6,%7},{%8,%9},{%0,%1,%2,%3};"
        : "+f"(c[0]), "+f"(c[1]), "+f"(c[2]), "+f"(c[3])
        : "r"(a[0]), "r"(a[1]), "r"(a[2]), "r"(a[3]), "r"(b0), "r"(b1));
}
// vector fp32 reduction (PTX ISA 8.1+, sm_90+): one 16B red instead of 4 scalar atomics
__device__ __forceinline__ void red_add_v4(float* gptr, float a, float b, float c, float d) {
    asm volatile("red.global.add.v4.f32 [%0], {%1, %2, %3, %4};"
                 :: "l"(gptr), "f"(a), "f"(b), "f"(c), "f"(d) : "memory");
}

// ---------------- fp16 tensor-core GEMM (2 CTAs/SM, 5-stage) ----------------
// C[M,768] = act(A[M,768] @ Wt^T + bias); A fp16 row-major, Wt fp16 [N][K] row-major.
// CTA tile 128(M) x 128(N), 256 threads (warps 4M x 2N, warp tile 32x64),
// BK=32 halves, 5-stage cp.async pipeline, ldmatrix operand loads.
#define BM 128
#define BN 128
#define BK 32
#define NT (D / BK)                      // 24
#define NSTAGE 5
#define SROW 80                          // smem row pitch bytes (40 halves) -> LDSM conflict-free
#define A_BYTES (BM * SROW)              // 10240
#define STAGE_BYTES (A_BYTES + BN * SROW)  // 20480
#define GEMM_THREADS 256
#define GEMM_SMEM (NSTAGE * STAGE_BYTES)   // 102400 (2 CTAs = 200KB <= 228KB)

template <int ACT, bool HOUT>
__global__ void __launch_bounds__(GEMM_THREADS, 2)
gemm_kernel(const __half* __restrict__ A, const __half* __restrict__ Wt,
            const float* __restrict__ bias, void* __restrict__ Cv, int M)
{
    extern __shared__ char smem[];
    const int t  = threadIdx.x;
    const int m0 = blockIdx.y * BM;
    const int n0 = blockIdx.x * BN;
    const uint32_t sbu = (uint32_t)__cvta_generic_to_shared(smem);

    auto load_stage = [&](int s, int kt) {
        char* abuf = smem + s * STAGE_BYTES;
        char* bbuf = abuf + A_BYTES;
        #pragma unroll
        for (int i = 0; i < 2; i++) {   // A: 128 rows x 64B = 512 chunks
            int q = t + i * GEMM_THREADS;
            int row = q >> 2, c = q & 3;
            int m = m0 + row; m = (m < M) ? m : (M - 1);
            cp_async16(abuf + row * SROW + c * 16, A + (size_t)m * D + kt * BK + c * 8);
        }
        #pragma unroll
        for (int i = 0; i < 2; i++) {   // B: 128 rows x 64B = 512 chunks
            int q = t + i * GEMM_THREADS;
            int row = q >> 2, c = q & 3;
            cp_async16(bbuf + row * SROW + c * 16, Wt + (size_t)(n0 + row) * D + kt * BK + c * 8);
        }
    };

    float acc[2][8][4];
    #pragma unroll
    for (int i = 0; i < 2; i++)
        #pragma unroll
        for (int j = 0; j < 8; j++)
            #pragma unroll
            for (int k = 0; k < 4; k++) acc[i][j][k] = 0.f;

    #pragma unroll
    for (int s = 0; s < NSTAGE; s++) {
        load_stage(s, s);
        asm volatile("cp.async.commit_group;" ::: "memory");
    }

    const int lane = t & 31, wid = t >> 5;
    const int wm = (wid & 3) * 32;      // warp M offset (4 warps over 128)
    const int wn = (wid >> 2) * 64;     // warp N offset (2 warps over 128)
    const int gr = lane >> 2, tig = lane & 3;

    // per-thread ldmatrix row offsets (bytes within tile)
    const uint32_t a_off0 = (uint32_t)((wm + (lane & 15)) * SROW + (lane >> 4) * 16);
    const uint32_t b_off0 = (uint32_t)((wn + (lane & 7) + ((lane >> 4) & 1) * 8) * SROW
                                       + ((lane >> 3) & 1) * 16);

    for (int kt = 0; kt < NT; ++kt) {
        const int s = kt % NSTAGE;
        asm volatile("cp.async.wait_group %0;" :: "n"(NSTAGE - 1) : "memory");
        __syncthreads();
        const uint32_t sa = sbu + s * STAGE_BYTES;
        const uint32_t sb = sa + A_BYTES;
        #pragma unroll
        for (int kc = 0; kc < 2; kc++) {           // two k16 sub-tiles
            uint32_t af[2][4];
            #pragma unroll
            for (int mi = 0; mi < 2; mi++)
                ldsm_x4(af[mi], sa + a_off0 + mi * 16 * SROW + kc * 32);
            #pragma unroll
            for (int jp = 0; jp < 4; jp++) {       // pairs of n-tiles
                uint32_t bf[4];
                ldsm_x4(bf, sb + b_off0 + jp * 16 * SROW + kc * 32);
                mma_f16(acc[0][jp * 2 + 0], af[0], bf[0], bf[1]);
                mma_f16(acc[1][jp * 2 + 0], af[1], bf[0], bf[1]);
                mma_f16(acc[0][jp * 2 + 1], af[0], bf[2], bf[3]);
                mma_f16(acc[1][jp * 2 + 1], af[1], bf[2], bf[3]);
            }
        }
        __syncthreads();                 // stage fully consumed before refill
        if (kt + NSTAGE < NT) load_stage(s, kt + NSTAGE);
        asm volatile("cp.async.commit_group;" ::: "memory");
    }

    // epilogue: bias + activation + store (fp16 for hidden/edge, fp32 otherwise)
    #pragma unroll
    for (int mi = 0; mi < 2; mi++) {
        int row0 = m0 + wm + mi * 16 + gr;
        #pragma unroll
        for (int ni = 0; ni < 8; ni++) {
            int col = n0 + wn + ni * 8 + tig * 2;
            float bv0 = __ldg(bias + col), bv1 = __ldg(bias + col + 1);
            float v0 = actf<ACT>(acc[mi][ni][0] + bv0);
            float v1 = actf<ACT>(acc[mi][ni][1] + bv1);
            float v2 = actf<ACT>(acc[mi][ni][2] + bv0);
            float v3 = actf<ACT>(acc[mi][ni][3] + bv1);
            if (HOUT) {
                __half* C = (__half*)Cv;
                if (row0 < M)
                    *(__half2*)(C + (size_t)row0 * D + col) = __floats2half2_rn(v0, v1);
                if (row0 + 8 < M)
                    *(__half2*)(C + (size_t)(row0 + 8) * D + col) = __floats2half2_rn(v2, v3);
            } else {
                float* C = (float*)Cv;
                if (row0 < M)
                    *(float2*)(C + (size_t)row0 * D + col) = make_float2(v0, v1);
                if (row0 + 8 < M)
                    *(float2*)(C + (size_t)(row0 + 8) * D + col) = make_float2(v2, v3);
            }
        }
    }
}

// ---------------- weight transpose + fp16 convert, all 12 matrices in ONE launch ----------------
struct WPtrs { const float* p[6]; };   // atom_w1, atom_w2, bond_w1, bond_w2, conv_w1, conv_w2
__global__ void transpose_all_kernel(WPtrs w, __half* __restrict__ wt) {
    int mat = blockIdx.z;
    const float* W = (mat < 4) ? w.p[mat]
                   : (mat < 8) ? w.p[4] + (size_t)(mat - 4) * D * D
                               : w.p[5] + (size_t)(mat - 8) * D * D;
    __half* Wt = wt + (size_t)mat * D * D;
    __shared__ float tile[32][33];
    int bx = blockIdx.x * 32;   // n block
    int by = blockIdx.y * 32;   // k block
    int tx = threadIdx.x, ty = threadIdx.y;   // 32 x 8
    #pragma unroll
    for (int j = 0; j < 32; j += 8)
        tile[ty + j][tx] = W[(size_t)(by + ty + j) * D + bx + tx];   // tile[k][n]
    __syncthreads();
    #pragma unroll
    for (int j = 0; j < 32; j += 8)
        Wt[(size_t)(bx + ty + j) * D + by + tx] = __float2half_rn(tile[tx][ty + j]);
}

// ---------------- fp32 -> fp16 convert (agg before conv GEMM) ----------------
__global__ void cvt_half_kernel(const float4* __restrict__ src, __half2* __restrict__ dst, int n4) {
    int i = blockIdx.x * blockDim.x + threadIdx.x;
    if (i < n4) {
        float4 v = src[i];
        dst[i * 2 + 0] = __floats2half2_rn(v.x, v.y);
        dst[i * 2 + 1] = __floats2half2_rn(v.z, v.w);
    }
}

// ---------------- seed: agg = h (fp32) and h16 = fp16(h), one pass ----------------
__global__ void seed_kernel(const float4* __restrict__ h, float4* __restrict__ agg,
                            __half2* __restrict__ h16, int n4) {
    int i = blockIdx.x * blockDim.x + threadIdx.x;
    if (i < n4) {
        float4 v = h[i];
        agg[i] = v;
        h16[i * 2 + 0] = __floats2half2_rn(v.x, v.y);
        h16[i * 2 + 1] = __floats2half2_rn(v.z, v.w);
    }
}

// ---------------- embedding sum + LayerNorm (fp16 output for GEMM) ----------------
__global__ void embed_ln_kernel(const int* __restrict__ ids,
                                const float* __restrict__ emb,
                                const float* __restrict__ g,
                                const float* __restrict__ bta,
                                __half* __restrict__ out,
                                int F, int V) {
    int n = blockIdx.x;
    int t = threadIdx.x;
    __shared__ int   sid[16];
    __shared__ float shm[16];
    if (t < F) sid[t] = ids[(size_t)n * F + t];
    __syncthreads();

    float x[3];
    #pragma unroll
    for (int j = 0; j < 3; j++) {
        int d = t + j * 256;
        float s = 0.f;
        for (int f = 0; f < F; f++)
            s += emb[((size_t)(f * V + sid[f])) * D + d];
        x[j] = s;
    }
    float s1 = x[0] + x[1] + x[2];
    float s2 = x[0]*x[0] + x[1]*x[1] + x[2]*x[2];
    block_reduce2(s1, s2, shm);
    float mean = s1 * (1.0f / D);
    float var  = s2 * (1.0f / D) - mean * mean;
    float inv  = rsqrtf(var + 1e-5f);
    __half* o = out + (size_t)n * D;
    #pragma unroll
    for (int j = 0; j < 3; j++) {
        int d = t + j * 256;
        o[d] = __float2half_rn((x[j] - mean) * inv * g[d] + bta[d]);
    }
}

// ---------------- edge message: agg[dst] += relu(h16[src] + e16), v4 reductions ----------------
__global__ void edge_msg_kernel(const int* __restrict__ ei,
                                const __half* __restrict__ h,
                                const __half* __restrict__ e,
                                float* __restrict__ agg, int E) {
    int eid = blockIdx.x;
    int src = __ldg(ei + eid);
    int dst = __ldg(ei + E + eid);
    int t = threadIdx.x;  // 192 threads * 4 halves = 768
    const __half2* hp = (const __half2*)(h + (size_t)src * D) + t * 2;
    const __half2* ep = (const __half2*)(e + (size_t)eid * D) + t * 2;
    float2 h0 = __half22float2(hp[0]);
    float2 h1 = __half22float2(hp[1]);
    float2 e0 = __half22float2(ep[0]);
    float2 e1 = __half22float2(ep[1]);
    float* a = agg + (size_t)dst * D + t * 4;   // 16B-aligned
    red_add_v4(a,
               fmaxf(h0.x + e0.x, 0.f),
               fmaxf(h0.y + e0.y, 0.f),
               fmaxf(h1.x + e1.x, 0.f),
               fmaxf(h1.y + e1.y, 0.f));
}

// ---------------- fused gelu + residual + LayerNorm (+ agg seed + h16 mirror) ----------------
__global__ void ln_res_kernel(const float* __restrict__ z,
                              const float* __restrict__ hin,
                              const float* __restrict__ g,
                              const float* __restrict__ bta,
                              float* __restrict__ out,
                              float* __restrict__ aggc,
                              __half* __restrict__ h16) {
    int n = blockIdx.x;
    int t = threadIdx.x;
    __shared__ float shm[16];
    float x[3];
    #pragma unroll
    for (int j = 0; j < 3; j++) {
        int d = t + j * 256;
        x[j] = gelu_f(z[(size_t)n * D + d]) + hin[(size_t)n * D + d];
    }
    float s1 = x[0] + x[1] + x[2];
    float s2 = x[0]*x[0] + x[1]*x[1] + x[2]*x[2];
    block_reduce2(s1, s2, shm);
    float mean = s1 * (1.0f / D);
    float var  = s2 * (1.0f / D) - mean * mean;
    float inv  = rsqrtf(var + 1e-5f);
    #pragma unroll
    for (int j = 0; j < 3; j++) {
        int d = t + j * 256;
        float r = (x[j] - mean) * inv * g[d] + bta[d];
        out[(size_t)n * D + d] = r;
        if (aggc) {
            aggc[(size_t)n * D + d] = r;
            h16[(size_t)n * D + d] = __float2half_rn(r);
        }
    }
}

// ---------------- host orchestration ----------------
extern "C" void kernel_launch(void* const* d_in, const int* in_sizes, int n_in,
                              void* d_out, int out_size) {
    const int*   x          = (const int*)d_in[0];
    const int*   edge_attr  = (const int*)d_in[1];
    const int*   edge_index = (const int*)d_in[2];
    const float* atom_emb   = (const float*)d_in[3];
    const float* atom_ln_g  = (const float*)d_in[4];
    const float* atom_ln_b  = (const float*)d_in[5];
    const float* atom_w1    = (const float*)d_in[6];
    const float* atom_b1    = (const float*)d_in[7];
    const float* atom_w2    = (const float*)d_in[8];
    const float* atom_b2    = (const float*)d_in[9];
    const float* bond_emb   = (const float*)d_in[10];
    const float* bond_ln_g  = (const float*)d_in[11];
    const float* bond_ln_b  = (const float*)d_in[12];
    const float* bond_w1    = (const float*)d_in[13];
    const float* bond_b1    = (const float*)d_in[14];
    const float* bond_w2    = (const float*)d_in[15];
    const float* bond_b2    = (const float*)d_in[16];
    const float* conv_w1    = (const float*)d_in[17];
    const float* conv_b1    = (const float*)d_in[18];
    const float* conv_w2    = (const float*)d_in[19];
    const float* conv_b2    = (const float*)d_in[20];
    const float* ln_g       = (const float*)d_in[21];
    const float* ln_b       = (const float*)d_in[22];
    float* out = (float*)d_out;

    int N = in_sizes[0] / 9;
    int E = in_sizes[1] / 3;
    if (N > MAXN) N = MAXN;
    if (E > MAXE) E = MAXE;

    float *phA, *phB, *pagg;
    __half *pe16, *ph16, *pa16, *pt16, *pw16;
    cudaGetSymbolAddress((void**)&phA,  g_hA);
    cudaGetSymbolAddress((void**)&phB,  g_hB);
    cudaGetSymbolAddress((void**)&pagg, g_agg);
    cudaGetSymbolAddress((void**)&pe16, g_e16);
    cudaGetSymbolAddress((void**)&ph16, g_h16);
    cudaGetSymbolAddress((void**)&pa16, g_a16);
    cudaGetSymbolAddress((void**)&pt16, g_t16);
    cudaGetSymbolAddress((void**)&pw16, g_w16);

    cudaFuncSetAttribute(gemm_kernel<0, false>, cudaFuncAttributeMaxDynamicSharedMemorySize, GEMM_SMEM);
    cudaFuncSetAttribute(gemm_kernel<0, true>,  cudaFuncAttributeMaxDynamicSharedMemorySize, GEMM_SMEM);
    cudaFuncSetAttribute(gemm_kernel<1, true>,  cudaFuncAttributeMaxDynamicSharedMemorySize, GEMM_SMEM);
    cudaFuncSetAttribute(gemm_kernel<2, true>,  cudaFuncAttributeMaxDynamicSharedMemorySize, GEMM_SMEM);

    // ---- launch 0: transpose + fp16-convert all 12 weight matrices ----
    WPtrs wp;
    wp.p[0] = atom_w1; wp.p[1] = atom_w2; wp.p[2] = bond_w1;
    wp.p[3] = bond_w2; wp.p[4] = conv_w1; wp.p[5] = conv_w2;
    transpose_all_kernel<<<dim3(D / 32, D / 32, 12), dim3(32, 8)>>>(wp, pw16);

    auto WT = [&](int i) { return pw16 + (size_t)i * D * D; };
    dim3 gN(D / BN, (N + BM - 1) / BM);
    dim3 gE(D / BN, (E + BM - 1) / BM);

    // ---- atom encode: h = enc(x) ----
    embed_ln_kernel<<<N, 256>>>(x, atom_emb, atom_ln_g, atom_ln_b, pa16, 9, 128);
    gemm_kernel<2, true ><<<gN, GEMM_THREADS, GEMM_SMEM>>>(pa16, WT(0), atom_b1, pt16, N);
    gemm_kernel<0, false><<<gN, GEMM_THREADS, GEMM_SMEM>>>(pt16, WT(1), atom_b2, phA, N);

    // ---- bond encode: e16 = enc(edge_attr), kept fp16 ----
    embed_ln_kernel<<<E, 256>>>(edge_attr, bond_emb, bond_ln_g, bond_ln_b, pa16, 3, 8);
    gemm_kernel<2, true ><<<gE, GEMM_THREADS, GEMM_SMEM>>>(pa16, WT(2), bond_b1, pt16, E);  // launch #5 -> ncu
    gemm_kernel<0, true ><<<gE, GEMM_THREADS, GEMM_SMEM>>>(pt16, WT(3), bond_b2, pe16, E);

    // ---- layer 0 seeds: agg = h, h16 = fp16(h) ----
    int n4 = N * D / 4;
    seed_kernel<<<(n4 + 255) / 256, 256>>>((const float4*)phA, (float4*)pagg, (__half2*)ph16, n4);

    const float* hcur = phA;
    float* hnext = phB;
    for (int l = 0; l < N_LAYERS; l++) {
        // agg += relu(h16[src] + e16)   (agg pre-seeded with h -> z = h + sum msg)
        edge_msg_kernel<<<E, 192>>>(edge_index, ph16, pe16, pagg, E);
        // convert z (=agg) to fp16 for the conv GEMM
        cvt_half_kernel<<<(n4 + 255) / 256, 256>>>((const float4*)pagg, (__half2*)pa16, n4);
        // conv MLP
        gemm_kernel<1, true ><<<gN, GEMM_THREADS, GEMM_SMEM>>>(pa16, WT(4 + l), conv_b1 + l * D, pt16, N);
        gemm_kernel<0, false><<<gN, GEMM_THREADS, GEMM_SMEM>>>(pt16, WT(8 + l), conv_b2 + l * D, pagg, N);
        // h = LN(gelu(z) + h_in); also seed next layer's agg and refresh h16 mirror
        float* dst  = (l == N_LAYERS - 1) ? out : hnext;
        float* aggc = (l == N_LAYERS - 1) ? nullptr : pagg;
        ln_res_kernel<<<N, 256>>>(pagg, hcur, ln_g + l * D, ln_b + l * D, dst, aggc, ph16);

        float* old = (float*)hcur;
        hcur = dst;
        hnext = old;
    }
}

// round 13
// speedup vs baseline: 1.5173x; 1.2928x over previous
#include <cuda_runtime.h>
#include <cuda_fp16.h>
#include <cstdint>
#include <cstddef>

#define D 768
#define N_LAYERS 4
#define MAXN 50000
#define MAXE 100000
#define NBOND 512   // 8^3 distinct edge-attr triples

// ---------------- static scratch (allocation-free rule) ----------------
__device__ float  g_hA [(size_t)MAXN * D];
__device__ float  g_hB [(size_t)MAXN * D];
__device__ float  g_agg[(size_t)MAXN * D];
__device__ int    g_code[(size_t)MAXE];                     // per-edge bond code
__device__ __align__(128) __half g_etab[(size_t)NBOND * D]; // bond-type table (fp16)
__device__ __align__(128) __half g_btmp[(size_t)2 * NBOND * D]; // bond encoder temps
__device__ __align__(128) __half g_h16[(size_t)MAXN * D];   // fp16 mirror of h (gather source)
__device__ __align__(128) __half g_a16[(size_t)MAXN * D];   // GEMM-1 inputs (fp16)
__device__ __align__(128) __half g_t16[(size_t)MAXN * D];   // hidden activations (fp16)
__device__ __align__(128) __half g_w16[(size_t)12 * D * D]; // transposed fp16 weights [n][k]

// ---------------- tiny helpers ----------------
__device__ __forceinline__ float gelu_f(float x) {
    const float k0 = 0.7978845608028654f;
    const float k1 = 0.044715f;
    return 0.5f * x * (1.0f + tanhf(k0 * (x + k1 * x * x * x)));
}
template <int ACT>
__device__ __forceinline__ float actf(float x) {
    if (ACT == 1) return fmaxf(x, 0.0f);
    if (ACT == 2) return gelu_f(x);
    return x;
}
__device__ __forceinline__ void block_reduce2(float& s1, float& s2, float* shm) {
    #pragma unroll
    for (int o = 16; o > 0; o >>= 1) {
        s1 += __shfl_xor_sync(0xffffffffu, s1, o);
        s2 += __shfl_xor_sync(0xffffffffu, s2, o);
    }
    int wid = threadIdx.x >> 5, lane = threadIdx.x & 31;
    if (lane == 0) { shm[wid] = s1; shm[8 + wid] = s2; }
    __syncthreads();
    float a = 0.f, b = 0.f;
    #pragma unroll
    for (int i = 0; i < 8; i++) { a += shm[i]; b += shm[8 + i]; }
    s1 = a; s2 = b;
}

__device__ __forceinline__ void cp_async16(void* s, const void* g) {
    uint32_t sa = (uint32_t)__cvta_generic_to_shared(s);
    asm volatile("cp.async.cg.shared.global [%0], [%1], 16;" :: "r"(sa), "l"(g));
}
__device__ __forceinline__ void ldsm_x4(uint32_t* r, uint32_t addr) {
    asm volatile("ldmatrix.sync.aligned.m8n8.x4.shared.b16 {%0,%1,%2,%3}, [%4];"
                 : "=r"(r[0]), "=r"(r[1]), "=r"(r[2]), "=r"(r[3]) : "r"(addr));
}
__device__ __forceinline__ void mma_f16(float* c, const uint32_t* a, uint32_t b0, uint32_t b1) {
    asm volatile(
        "mma.sync.aligned.m16n8k16.row.col.f32.f16.f16.f32 "
        "{%0,%1,%2,%3},{%4,%5,%6,%7},{%8,%9},{%0,%1,%2,%3};"
        : "+f"(c[0]), "+f"(c[1]), "+f"(c[2]), "+f"(c[3])
        : "r"(a[0]), "r"(a[1]), "r"(a[2]), "r"(a[3]), "r"(b0), "r"(b1));
}
// vector fp32 reduction (PTX ISA 8.1+, sm_90+)
__device__ __forceinline__ void red_add_v4(float* gptr, float a, float b, float c, float d) {
    asm volatile("red.global.add.v4.f32 [%0], {%1, %2, %3, %4};"
                 :: "l"(gptr), "f"(a), "f"(b), "f"(c), "f"(d) : "memory");
}

// ---------------- fp16 tensor-core GEMM (2 CTAs/SM, 5-stage) ----------------
#define BM 128
#define BN 128
#define BK 32
#define NT (D / BK)                      // 24
#define NSTAGE 5
#define SROW 80                          // smem row pitch bytes -> LDSM conflict-free
#define A_BYTES (BM * SROW)              // 10240
#define STAGE_BYTES (A_BYTES + BN * SROW)  // 20480
#define GEMM_THREADS 256
#define GEMM_SMEM (NSTAGE * STAGE_BYTES)   // 102400 (2 CTAs = 200KB <= 228KB)

template <int ACT, bool HOUT>
__global__ void __launch_bounds__(GEMM_THREADS, 2)
gemm_kernel(const __half* __restrict__ A, const __half* __restrict__ Wt,
            const float* __restrict__ bias, void* __restrict__ Cv, int M)
{
    extern __shared__ char smem[];
    const int t  = threadIdx.x;
    const int m0 = blockIdx.y * BM;
    const int n0 = blockIdx.x * BN;
    const uint32_t sbu = (uint32_t)__cvta_generic_to_shared(smem);

    auto load_stage = [&](int s, int kt) {
        char* abuf = smem + s * STAGE_BYTES;
        char* bbuf = abuf + A_BYTES;
        #pragma unroll
        for (int i = 0; i < 2; i++) {   // A: 128 rows x 64B
            int q = t + i * GEMM_THREADS;
            int row = q >> 2, c = q & 3;
            int m = m0 + row; m = (m < M) ? m : (M - 1);
            cp_async16(abuf + row * SROW + c * 16, A + (size_t)m * D + kt * BK + c * 8);
        }
        #pragma unroll
        for (int i = 0; i < 2; i++) {   // B: 128 rows x 64B
            int q = t + i * GEMM_THREADS;
            int row = q >> 2, c = q & 3;
            cp_async16(bbuf + row * SROW + c * 16, Wt + (size_t)(n0 + row) * D + kt * BK + c * 8);
        }
    };

    float acc[2][8][4];
    #pragma unroll
    for (int i = 0; i < 2; i++)
        #pragma unroll
        for (int j = 0; j < 8; j++)
            #pragma unroll
            for (int k = 0; k < 4; k++) acc[i][j][k] = 0.f;

    #pragma unroll
    for (int s = 0; s < NSTAGE; s++) {
        load_stage(s, s);
        asm volatile("cp.async.commit_group;" ::: "memory");
    }

    const int lane = t & 31, wid = t >> 5;
    const int wm = (wid & 3) * 32;      // 4 warps over M(128)
    const int wn = (wid >> 2) * 64;     // 2 warps over N(128)
    const int gr = lane >> 2, tig = lane & 3;

    const uint32_t a_off0 = (uint32_t)((wm + (lane & 15)) * SROW + (lane >> 4) * 16);
    const uint32_t b_off0 = (uint32_t)((wn + (lane & 7) + ((lane >> 4) & 1) * 8) * SROW
                                       + ((lane >> 3) & 1) * 16);

    for (int kt = 0; kt < NT; ++kt) {
        const int s = kt % NSTAGE;
        asm volatile("cp.async.wait_group %0;" :: "n"(NSTAGE - 1) : "memory");
        __syncthreads();
        const uint32_t sa = sbu + s * STAGE_BYTES;
        const uint32_t sb = sa + A_BYTES;
        #pragma unroll
        for (int kc = 0; kc < 2; kc++) {
            uint32_t af[2][4];
            #pragma unroll
            for (int mi = 0; mi < 2; mi++)
                ldsm_x4(af[mi], sa + a_off0 + mi * 16 * SROW + kc * 32);
            #pragma unroll
            for (int jp = 0; jp < 4; jp++) {
                uint32_t bf[4];
                ldsm_x4(bf, sb + b_off0 + jp * 16 * SROW + kc * 32);
                mma_f16(acc[0][jp * 2 + 0], af[0], bf[0], bf[1]);
                mma_f16(acc[1][jp * 2 + 0], af[1], bf[0], bf[1]);
                mma_f16(acc[0][jp * 2 + 1], af[0], bf[2], bf[3]);
                mma_f16(acc[1][jp * 2 + 1], af[1], bf[2], bf[3]);
            }
        }
        __syncthreads();
        if (kt + NSTAGE < NT) load_stage(s, kt + NSTAGE);
        asm volatile("cp.async.commit_group;" ::: "memory");
    }

    #pragma unroll
    for (int mi = 0; mi < 2; mi++) {
        int row0 = m0 + wm + mi * 16 + gr;
        #pragma unroll
        for (int ni = 0; ni < 8; ni++) {
            int col = n0 + wn + ni * 8 + tig * 2;
            float bv0 = __ldg(bias + col), bv1 = __ldg(bias + col + 1);
            float v0 = actf<ACT>(acc[mi][ni][0] + bv0);
            float v1 = actf<ACT>(acc[mi][ni][1] + bv1);
            float v2 = actf<ACT>(acc[mi][ni][2] + bv0);
            float v3 = actf<ACT>(acc[mi][ni][3] + bv1);
            if (HOUT) {
                __half* C = (__half*)Cv;
                if (row0 < M)
                    *(__half2*)(C + (size_t)row0 * D + col) = __floats2half2_rn(v0, v1);
                if (row0 + 8 < M)
                    *(__half2*)(C + (size_t)(row0 + 8) * D + col) = __floats2half2_rn(v2, v3);
            } else {
                float* C = (float*)Cv;
                if (row0 < M)
                    *(float2*)(C + (size_t)row0 * D + col) = make_float2(v0, v1);
                if (row0 + 8 < M)
                    *(float2*)(C + (size_t)(row0 + 8) * D + col) = make_float2(v2, v3);
            }
        }
    }
}

// ---------------- weight transpose + fp16 convert, all 12 matrices in ONE launch ----------------
struct WPtrs { const float* p[6]; };
__global__ void transpose_all_kernel(WPtrs w, __half* __restrict__ wt) {
    int mat = blockIdx.z;
    const float* W = (mat < 4) ? w.p[mat]
                   : (mat < 8) ? w.p[4] + (size_t)(mat - 4) * D * D
                               : w.p[5] + (size_t)(mat - 8) * D * D;
    __half* Wt = wt + (size_t)mat * D * D;
    __shared__ float tile[32][33];
    int bx = blockIdx.x * 32;
    int by = blockIdx.y * 32;
    int tx = threadIdx.x, ty = threadIdx.y;
    #pragma unroll
    for (int j = 0; j < 32; j += 8)
        tile[ty + j][tx] = W[(size_t)(by + ty + j) * D + bx + tx];
    __syncthreads();
    #pragma unroll
    for (int j = 0; j < 32; j += 8)
        Wt[(size_t)(bx + ty + j) * D + by + tx] = __float2half_rn(tile[tx][ty + j]);
}

// ---------------- fp32 -> fp16 convert (agg before conv GEMM) ----------------
__global__ void cvt_half_kernel(const float4* __restrict__ src, __half2* __restrict__ dst, int n4) {
    int i = blockIdx.x * blockDim.x + threadIdx.x;
    if (i < n4) {
        float4 v = src[i];
        dst[i * 2 + 0] = __floats2half2_rn(v.x, v.y);
        dst[i * 2 + 1] = __floats2half2_rn(v.z, v.w);
    }
}

// ---------------- seed: agg = h (fp32) and h16 = fp16(h), one pass ----------------
__global__ void seed_kernel(const float4* __restrict__ h, float4* __restrict__ agg,
                            __half2* __restrict__ h16, int n4) {
    int i = blockIdx.x * blockDim.x + threadIdx.x;
    if (i < n4) {
        float4 v = h[i];
        agg[i] = v;
        h16[i * 2 + 0] = __floats2half2_rn(v.x, v.y);
        h16[i * 2 + 1] = __floats2half2_rn(v.z, v.w);
    }
}

// ---------------- per-edge bond code ----------------
__global__ void code_kernel(const int* __restrict__ ea, int* __restrict__ code, int E) {
    int i = blockIdx.x * blockDim.x + threadIdx.x;
    if (i < E)
        code[i] = ea[i * 3] * 64 + ea[i * 3 + 1] * 8 + ea[i * 3 + 2];
}

// ---------------- embedding sum + LayerNorm (atom path, fp16 out) ----------------
__global__ void embed_ln_kernel(const int* __restrict__ ids,
                                const float* __restrict__ emb,
                                const float* __restrict__ g,
                                const float* __restrict__ bta,
                                __half* __restrict__ out,
                                int F, int V) {
    int n = blockIdx.x;
    int t = threadIdx.x;
    __shared__ int   sid[16];
    __shared__ float shm[16];
    if (t < F) sid[t] = ids[(size_t)n * F + t];
    __syncthreads();

    float x[3];
    #pragma unroll
    for (int j = 0; j < 3; j++) {
        int d = t + j * 256;
        float s = 0.f;
        for (int f = 0; f < F; f++)
            s += emb[((size_t)(f * V + sid[f])) * D + d];
        x[j] = s;
    }
    float s1 = x[0] + x[1] + x[2];
    float s2 = x[0]*x[0] + x[1]*x[1] + x[2]*x[2];
    block_reduce2(s1, s2, shm);
    float mean = s1 * (1.0f / D);
    float var  = s2 * (1.0f / D) - mean * mean;
    float inv  = rsqrtf(var + 1e-5f);
    __half* o = out + (size_t)n * D;
    #pragma unroll
    for (int j = 0; j < 3; j++) {
        int d = t + j * 256;
        o[d] = __float2half_rn((x[j] - mean) * inv * g[d] + bta[d]);
    }
}

// ---------------- bond table embed+LN: one block per code in [0,512) ----------------
__global__ void embed_ln_bond_kernel(const float* __restrict__ emb,
                                     const float* __restrict__ g,
                                     const float* __restrict__ bta,
                                     __half* __restrict__ out) {
    int n = blockIdx.x;                 // bond code
    int t = threadIdx.x;
    __shared__ float shm[16];
    int id0 = (n >> 6) & 7, id1 = (n >> 3) & 7, id2 = n & 7;

    float x[3];
    #pragma unroll
    for (int j = 0; j < 3; j++) {
        int d = t + j * 256;
        x[j] = emb[((size_t)(0 * 8 + id0)) * D + d]
             + emb[((size_t)(1 * 8 + id1)) * D + d]
             + emb[((size_t)(2 * 8 + id2)) * D + d];
    }
    float s1 = x[0] + x[1] + x[2];
    float s2 = x[0]*x[0] + x[1]*x[1] + x[2]*x[2];
    block_reduce2(s1, s2, shm);
    float mean = s1 * (1.0f / D);
    float var  = s2 * (1.0f / D) - mean * mean;
    float inv  = rsqrtf(var + 1e-5f);
    __half* o = out + (size_t)n * D;
    #pragma unroll
    for (int j = 0; j < 3; j++) {
        int d = t + j * 256;
        o[d] = __float2half_rn((x[j] - mean) * inv * g[d] + bta[d]);
    }
}

// ---------------- edge message: agg[dst] += relu(h16[src] + etab[code]) ----------------
__global__ void edge_msg_kernel(const int* __restrict__ ei,
                                const __half* __restrict__ h,
                                const __half* __restrict__ etab,
                                const int* __restrict__ code,
                                float* __restrict__ agg, int E) {
    int eid = blockIdx.x;
    int src = __ldg(ei + eid);
    int dst = __ldg(ei + E + eid);
    int c   = __ldg(code + eid);
    int t = threadIdx.x;  // 192 threads * 4 halves = 768
    const __half2* hp = (const __half2*)(h + (size_t)src * D) + t * 2;
    const __half2* ep = (const __half2*)(etab + (size_t)c * D) + t * 2;
    float2 h0 = __half22float2(hp[0]);
    float2 h1 = __half22float2(hp[1]);
    float2 e0 = __half22float2(ep[0]);
    float2 e1 = __half22float2(ep[1]);
    float* a = agg + (size_t)dst * D + t * 4;
    red_add_v4(a,
               fmaxf(h0.x + e0.x, 0.f),
               fmaxf(h0.y + e0.y, 0.f),
               fmaxf(h1.x + e1.x, 0.f),
               fmaxf(h1.y + e1.y, 0.f));
}

// ---------------- fused gelu + residual + LayerNorm (+ agg seed + h16 mirror) ----------------
__global__ void ln_res_kernel(const float* __restrict__ z,
                              const float* __restrict__ hin,
                              const float* __restrict__ g,
                              const float* __restrict__ bta,
                              float* __restrict__ out,
                              float* __restrict__ aggc,
                              __half* __restrict__ h16) {
    int n = blockIdx.x;
    int t = threadIdx.x;
    __shared__ float shm[16];
    float x[3];
    #pragma unroll
    for (int j = 0; j < 3; j++) {
        int d = t + j * 256;
        x[j] = gelu_f(z[(size_t)n * D + d]) + hin[(size_t)n * D + d];
    }
    float s1 = x[0] + x[1] + x[2];
    float s2 = x[0]*x[0] + x[1]*x[1] + x[2]*x[2];
    block_reduce2(s1, s2, shm);
    float mean = s1 * (1.0f / D);
    float var  = s2 * (1.0f / D) - mean * mean;
    float inv  = rsqrtf(var + 1e-5f);
    #pragma unroll
    for (int j = 0; j < 3; j++) {
        int d = t + j * 256;
        float r = (x[j] - mean) * inv * g[d] + bta[d];
        out[(size_t)n * D + d] = r;
        if (aggc) {
            aggc[(size_t)n * D + d] = r;
            h16[(size_t)n * D + d] = __float2half_rn(r);
        }
    }
}

// ---------------- host orchestration ----------------
extern "C" void kernel_launch(void* const* d_in, const int* in_sizes, int n_in,
                              void* d_out, int out_size) {
    const int*   x          = (const int*)d_in[0];
    const int*   edge_attr  = (const int*)d_in[1];
    const int*   edge_index = (const int*)d_in[2];
    const float* atom_emb   = (const float*)d_in[3];
    const float* atom_ln_g  = (const float*)d_in[4];
    const float* atom_ln_b  = (const float*)d_in[5];
    const float* atom_w1    = (const float*)d_in[6];
    const float* atom_b1    = (const float*)d_in[7];
    const float* atom_w2    = (const float*)d_in[8];
    const float* atom_b2    = (const float*)d_in[9];
    const float* bond_emb   = (const float*)d_in[10];
    const float* bond_ln_g  = (const float*)d_in[11];
    const float* bond_ln_b  = (const float*)d_in[12];
    const float* bond_w1    = (const float*)d_in[13];
    const float* bond_b1    = (const float*)d_in[14];
    const float* bond_w2    = (const float*)d_in[15];
    const float* bond_b2    = (const float*)d_in[16];
    const float* conv_w1    = (const float*)d_in[17];
    const float* conv_b1    = (const float*)d_in[18];
    const float* conv_w2    = (const float*)d_in[19];
    const float* conv_b2    = (const float*)d_in[20];
    const float* ln_g       = (const float*)d_in[21];
    const float* ln_b       = (const float*)d_in[22];
    float* out = (float*)d_out;

    int N = in_sizes[0] / 9;
    int E = in_sizes[1] / 3;
    if (N > MAXN) N = MAXN;
    if (E > MAXE) E = MAXE;

    float *phA, *phB, *pagg;
    int *pcode;
    __half *petab, *pbtmp, *ph16, *pa16, *pt16, *pw16;
    cudaGetSymbolAddress((void**)&phA,   g_hA);
    cudaGetSymbolAddress((void**)&phB,   g_hB);
    cudaGetSymbolAddress((void**)&pagg,  g_agg);
    cudaGetSymbolAddress((void**)&pcode, g_code);
    cudaGetSymbolAddress((void**)&petab, g_etab);
    cudaGetSymbolAddress((void**)&pbtmp, g_btmp);
    cudaGetSymbolAddress((void**)&ph16,  g_h16);
    cudaGetSymbolAddress((void**)&pa16,  g_a16);
    cudaGetSymbolAddress((void**)&pt16,  g_t16);
    cudaGetSymbolAddress((void**)&pw16,  g_w16);

    cudaFuncSetAttribute(gemm_kernel<0, false>, cudaFuncAttributeMaxDynamicSharedMemorySize, GEMM_SMEM);
    cudaFuncSetAttribute(gemm_kernel<0, true>,  cudaFuncAttributeMaxDynamicSharedMemorySize, GEMM_SMEM);
    cudaFuncSetAttribute(gemm_kernel<1, true>,  cudaFuncAttributeMaxDynamicSharedMemorySize, GEMM_SMEM);
    cudaFuncSetAttribute(gemm_kernel<2, true>,  cudaFuncAttributeMaxDynamicSharedMemorySize, GEMM_SMEM);

    // ---- launch 0: transpose + fp16-convert all 12 weight matrices ----
    WPtrs wp;
    wp.p[0] = atom_w1; wp.p[1] = atom_w2; wp.p[2] = bond_w1;
    wp.p[3] = bond_w2; wp.p[4] = conv_w1; wp.p[5] = conv_w2;
    transpose_all_kernel<<<dim3(D / 32, D / 32, 12), dim3(32, 8)>>>(wp, pw16);

    auto WT = [&](int i) { return pw16 + (size_t)i * D * D; };
    dim3 gN(D / BN, (N + BM - 1) / BM);
    dim3 gB(D / BN, (NBOND + BM - 1) / BM);   // 512-row bond-table GEMMs

    // launches 1-3: atom embed, bond-table embed, edge codes
    embed_ln_kernel<<<N, 256>>>(x, atom_emb, atom_ln_g, atom_ln_b, pa16, 9, 128);
    embed_ln_bond_kernel<<<NBOND, 256>>>(bond_emb, bond_ln_g, bond_ln_b, pbtmp);
    code_kernel<<<(E + 255) / 256, 256>>>(edge_attr, pcode, E);

    // launches 4-5: atom encoder GEMMs (launch #5 = full N-GEMM -> ncu)
    gemm_kernel<2, true ><<<gN, GEMM_THREADS, GEMM_SMEM>>>(pa16, WT(0), atom_b1, pt16, N);
    gemm_kernel<0, false><<<gN, GEMM_THREADS, GEMM_SMEM>>>(pt16, WT(1), atom_b2, phA, N);

    // bond-table encoder GEMMs over 512 rows (tiny)
    gemm_kernel<2, true ><<<gB, GEMM_THREADS, GEMM_SMEM>>>(pbtmp, WT(2), bond_b1, pbtmp + (size_t)NBOND * D, NBOND);
    gemm_kernel<0, true ><<<gB, GEMM_THREADS, GEMM_SMEM>>>(pbtmp + (size_t)NBOND * D, WT(3), bond_b2, petab, NBOND);

    // ---- layer 0 seeds: agg = h, h16 = fp16(h) ----
    int n4 = N * D / 4;
    seed_kernel<<<(n4 + 255) / 256, 256>>>((const float4*)phA, (float4*)pagg, (__half2*)ph16, n4);

    const float* hcur = phA;
    float* hnext = phB;
    for (int l = 0; l < N_LAYERS; l++) {
        // agg += relu(h16[src] + etab[code])   (agg pre-seeded with h)
        edge_msg_kernel<<<E, 192>>>(edge_index, ph16, petab, pcode, pagg, E);
        // convert z (=agg) to fp16 for the conv GEMM
        cvt_half_kernel<<<(n4 + 255) / 256, 256>>>((const float4*)pagg, (__half2*)pa16, n4);
        // conv MLP
        gemm_kernel<1, true ><<<gN, GEMM_THREADS, GEMM_SMEM>>>(pa16, WT(4 + l), conv_b1 + l * D, pt16, N);
        gemm_kernel<0, false><<<gN, GEMM_THREADS, GEMM_SMEM>>>(pt16, WT(8 + l), conv_b2 + l * D, pagg, N);
        // h = LN(gelu(z) + h_in); also seed next layer's agg and refresh h16 mirror
        float* dst  = (l == N_LAYERS - 1) ? out : hnext;
        float* aggc = (l == N_LAYERS - 1) ? nullptr : pagg;
        ln_res_kernel<<<N, 256>>>(pagg, hcur, ln_g + l * D, ln_b + l * D, dst, aggc, ph16);

        float* old = (float*)hcur;
        hcur = dst;
        hnext = old;
    }
}

// round 14
// speedup vs baseline: 1.6728x; 1.1024x over previous
#include <cuda_runtime.h>
#include <cuda_fp16.h>
#include <cstdint>
#include <cstddef>

#define D 768
#define N_LAYERS 4
#define MAXN 50000
#define MAXE 100000
#define NBOND 512   // 8^3 distinct edge-attr triples

// ---------------- static scratch (allocation-free rule) ----------------
__device__ float  g_hA [(size_t)MAXN * D];
__device__ float  g_hB [(size_t)MAXN * D];
__device__ float  g_z  [(size_t)MAXN * D];                  // conv-MLP output (fp32)
__device__ int    g_hist[(size_t)MAXN];
__device__ int    g_cnt [(size_t)MAXN];
__device__ int    g_rowstart[(size_t)MAXN + 1];
__device__ int    g_srcs [(size_t)MAXE];
__device__ int    g_codes[(size_t)MAXE];
__device__ __align__(128) __half g_etab[(size_t)NBOND * D]; // bond-type table (fp16)
__device__ __align__(128) __half g_btmp[(size_t)2 * NBOND * D];
__device__ __align__(128) __half g_h16[(size_t)MAXN * D];   // fp16 mirror of h
__device__ __align__(128) __half g_a16[(size_t)MAXN * D];   // GEMM-1 inputs (fp16)
__device__ __align__(128) __half g_t16[(size_t)MAXN * D];   // hidden activations (fp16)
__device__ __align__(128) __half g_w16[(size_t)12 * D * D]; // transposed fp16 weights [n][k]

// ---------------- tiny helpers ----------------
__device__ __forceinline__ float gelu_f(float x) {
    const float k0 = 0.7978845608028654f;
    const float k1 = 0.044715f;
    return 0.5f * x * (1.0f + tanhf(k0 * (x + k1 * x * x * x)));
}
template <int ACT>
__device__ __forceinline__ float actf(float x) {
    if (ACT == 1) return fmaxf(x, 0.0f);
    if (ACT == 2) return gelu_f(x);
    return x;
}
__device__ __forceinline__ void block_reduce2(float& s1, float& s2, float* shm) {
    #pragma unroll
    for (int o = 16; o > 0; o >>= 1) {
        s1 += __shfl_xor_sync(0xffffffffu, s1, o);
        s2 += __shfl_xor_sync(0xffffffffu, s2, o);
    }
    int wid = threadIdx.x >> 5, lane = threadIdx.x & 31;
    if (lane == 0) { shm[wid] = s1; shm[8 + wid] = s2; }
    __syncthreads();
    float a = 0.f, b = 0.f;
    #pragma unroll
    for (int i = 0; i < 8; i++) { a += shm[i]; b += shm[8 + i]; }
    s1 = a; s2 = b;
}

__device__ __forceinline__ void cp_async16(void* s, const void* g) {
    uint32_t sa = (uint32_t)__cvta_generic_to_shared(s);
    asm volatile("cp.async.cg.shared.global [%0], [%1], 16;" :: "r"(sa), "l"(g));
}
__device__ __forceinline__ void ldsm_x4(uint32_t* r, uint32_t addr) {
    asm volatile("ldmatrix.sync.aligned.m8n8.x4.shared.b16 {%0,%1,%2,%3}, [%4];"
                 : "=r"(r[0]), "=r"(r[1]), "=r"(r[2]), "=r"(r[3]) : "r"(addr));
}
__device__ __forceinline__ void mma_f16(float* c, const uint32_t* a, uint32_t b0, uint32_t b1) {
    asm volatile(
        "mma.sync.aligned.m16n8k16.row.col.f32.f16.f16.f32 "
        "{%0,%1,%2,%3},{%4,%5,%6,%7},{%8,%9},{%0,%1,%2,%3};"
        : "+f"(c[0]), "+f"(c[1]), "+f"(c[2]), "+f"(c[3])
        : "r"(a[0]), "r"(a[1]), "r"(a[2]), "r"(a[3]), "r"(b0), "r"(b1));
}

// ---------------- fp16 tensor-core GEMM (2 CTAs/SM, 5-stage) ----------------
#define BM 128
#define BN 128
#define BK 32
#define NT (D / BK)                      // 24
#define NSTAGE 5
#define SROW 80
#define A_BYTES (BM * SROW)              // 10240
#define STAGE_BYTES (A_BYTES + BN * SROW)  // 20480
#define GEMM_THREADS 256
#define GEMM_SMEM (NSTAGE * STAGE_BYTES)   // 102400

template <int ACT, bool HOUT>
__global__ void __launch_bounds__(GEMM_THREADS, 2)
gemm_kernel(const __half* __restrict__ A, const __half* __restrict__ Wt,
            const float* __restrict__ bias, void* __restrict__ Cv, int M)
{
    extern __shared__ char smem[];
    const int t  = threadIdx.x;
    const int m0 = blockIdx.y * BM;
    const int n0 = blockIdx.x * BN;
    const uint32_t sbu = (uint32_t)__cvta_generic_to_shared(smem);

    auto load_stage = [&](int s, int kt) {
        char* abuf = smem + s * STAGE_BYTES;
        char* bbuf = abuf + A_BYTES;
        #pragma unroll
        for (int i = 0; i < 2; i++) {
            int q = t + i * GEMM_THREADS;
            int row = q >> 2, c = q & 3;
            int m = m0 + row; m = (m < M) ? m : (M - 1);
            cp_async16(abuf + row * SROW + c * 16, A + (size_t)m * D + kt * BK + c * 8);
        }
        #pragma unroll
        for (int i = 0; i < 2; i++) {
            int q = t + i * GEMM_THREADS;
            int row = q >> 2, c = q & 3;
            cp_async16(bbuf + row * SROW + c * 16, Wt + (size_t)(n0 + row) * D + kt * BK + c * 8);
        }
    };

    float acc[2][8][4];
    #pragma unroll
    for (int i = 0; i < 2; i++)
        #pragma unroll
        for (int j = 0; j < 8; j++)
            #pragma unroll
            for (int k = 0; k < 4; k++) acc[i][j][k] = 0.f;

    #pragma unroll
    for (int s = 0; s < NSTAGE; s++) {
        load_stage(s, s);
        asm volatile("cp.async.commit_group;" ::: "memory");
    }

    const int lane = t & 31, wid = t >> 5;
    const int wm = (wid & 3) * 32;
    const int wn = (wid >> 2) * 64;
    const int gr = lane >> 2, tig = lane & 3;

    const uint32_t a_off0 = (uint32_t)((wm + (lane & 15)) * SROW + (lane >> 4) * 16);
    const uint32_t b_off0 = (uint32_t)((wn + (lane & 7) + ((lane >> 4) & 1) * 8) * SROW
                                       + ((lane >> 3) & 1) * 16);

    for (int kt = 0; kt < NT; ++kt) {
        const int s = kt % NSTAGE;
        asm volatile("cp.async.wait_group %0;" :: "n"(NSTAGE - 1) : "memory");
        __syncthreads();
        const uint32_t sa = sbu + s * STAGE_BYTES;
        const uint32_t sb = sa + A_BYTES;
        #pragma unroll
        for (int kc = 0; kc < 2; kc++) {
            uint32_t af[2][4];
            #pragma unroll
            for (int mi = 0; mi < 2; mi++)
                ldsm_x4(af[mi], sa + a_off0 + mi * 16 * SROW + kc * 32);
            #pragma unroll
            for (int jp = 0; jp < 4; jp++) {
                uint32_t bf[4];
                ldsm_x4(bf, sb + b_off0 + jp * 16 * SROW + kc * 32);
                mma_f16(acc[0][jp * 2 + 0], af[0], bf[0], bf[1]);
                mma_f16(acc[1][jp * 2 + 0], af[1], bf[0], bf[1]);
                mma_f16(acc[0][jp * 2 + 1], af[0], bf[2], bf[3]);
                mma_f16(acc[1][jp * 2 + 1], af[1], bf[2], bf[3]);
            }
        }
        __syncthreads();
        if (kt + NSTAGE < NT) load_stage(s, kt + NSTAGE);
        asm volatile("cp.async.commit_group;" ::: "memory");
    }

    #pragma unroll
    for (int mi = 0; mi < 2; mi++) {
        int row0 = m0 + wm + mi * 16 + gr;
        #pragma unroll
        for (int ni = 0; ni < 8; ni++) {
            int col = n0 + wn + ni * 8 + tig * 2;
            float bv0 = __ldg(bias + col), bv1 = __ldg(bias + col + 1);
            float v0 = actf<ACT>(acc[mi][ni][0] + bv0);
            float v1 = actf<ACT>(acc[mi][ni][1] + bv1);
            float v2 = actf<ACT>(acc[mi][ni][2] + bv0);
            float v3 = actf<ACT>(acc[mi][ni][3] + bv1);
            if (HOUT) {
                __half* C = (__half*)Cv;
                if (row0 < M)
                    *(__half2*)(C + (size_t)row0 * D + col) = __floats2half2_rn(v0, v1);
                if (row0 + 8 < M)
                    *(__half2*)(C + (size_t)(row0 + 8) * D + col) = __floats2half2_rn(v2, v3);
            } else {
                float* C = (float*)Cv;
                if (row0 < M)
                    *(float2*)(C + (size_t)row0 * D + col) = make_float2(v0, v1);
                if (row0 + 8 < M)
                    *(float2*)(C + (size_t)(row0 + 8) * D + col) = make_float2(v2, v3);
            }
        }
    }
}

// ---------------- weight transpose + fp16 convert (one launch) ----------------
struct WPtrs { const float* p[6]; };
__global__ void transpose_all_kernel(WPtrs w, __half* __restrict__ wt) {
    int mat = blockIdx.z;
    const float* W = (mat < 4) ? w.p[mat]
                   : (mat < 8) ? w.p[4] + (size_t)(mat - 4) * D * D
                               : w.p[5] + (size_t)(mat - 8) * D * D;
    __half* Wt = wt + (size_t)mat * D * D;
    __shared__ float tile[32][33];
    int bx = blockIdx.x * 32;
    int by = blockIdx.y * 32;
    int tx = threadIdx.x, ty = threadIdx.y;
    #pragma unroll
    for (int j = 0; j < 32; j += 8)
        tile[ty + j][tx] = W[(size_t)(by + ty + j) * D + bx + tx];
    __syncthreads();
    #pragma unroll
    for (int j = 0; j < 32; j += 8)
        Wt[(size_t)(bx + ty + j) * D + by + tx] = __float2half_rn(tile[tx][ty + j]);
}

// ---------------- CSR build ----------------
__global__ void zero2_kernel(int* __restrict__ a, int* __restrict__ b, int n) {
    int i = blockIdx.x * blockDim.x + threadIdx.x;
    if (i < n) { a[i] = 0; b[i] = 0; }
}
__global__ void hist_kernel(const int* __restrict__ ei, int* __restrict__ hist, int E) {
    int i = blockIdx.x * blockDim.x + threadIdx.x;
    if (i < E) atomicAdd(hist + ei[E + i], 1);
}
// single-block exclusive scan of hist[0..n) -> rowstart[0..n], 1024 threads
__global__ void scan_kernel(const int* __restrict__ hist, int* __restrict__ rowstart, int n) {
    __shared__ int wsum[32];
    __shared__ int s_carry;
    int t = threadIdx.x;
    int lane = t & 31, w = t >> 5;
    if (t == 0) s_carry = 0;
    __syncthreads();
    for (int base = 0; base < n; base += 1024) {
        int idx = base + t;
        int v = (idx < n) ? hist[idx] : 0;
        int x = v;
        #pragma unroll
        for (int o = 1; o < 32; o <<= 1) {
            int y = __shfl_up_sync(0xffffffffu, x, o);
            if (lane >= o) x += y;
        }
        if (lane == 31) wsum[w] = x;
        __syncthreads();
        if (w == 0) {
            int s = wsum[lane];
            #pragma unroll
            for (int o = 1; o < 32; o <<= 1) {
                int y = __shfl_up_sync(0xffffffffu, s, o);
                if (lane >= o) s += y;
            }
            wsum[lane] = s;
        }
        __syncthreads();
        int incl = x + (w > 0 ? wsum[w - 1] : 0);
        int carry = s_carry;
        if (idx < n) rowstart[idx] = carry + incl - v;
        __syncthreads();
        if (t == 0) s_carry = carry + wsum[31];
        __syncthreads();
    }
    if (t == 0) rowstart[n] = s_carry;
}
__global__ void scatter_kernel(const int* __restrict__ ei, const int* __restrict__ ea,
                               const int* __restrict__ rowstart, int* __restrict__ cnt,
                               int* __restrict__ srcs, int* __restrict__ codes, int E) {
    int i = blockIdx.x * blockDim.x + threadIdx.x;
    if (i < E) {
        int dst = ei[E + i];
        int pos = rowstart[dst] + atomicAdd(cnt + dst, 1);
        srcs[pos]  = ei[i];
        codes[pos] = ea[i * 3] * 64 + ea[i * 3 + 1] * 8 + ea[i * 3 + 2];
    }
}

// ---------------- seed: h16 = fp16(h) ----------------
__global__ void seed_kernel(const float4* __restrict__ h, __half2* __restrict__ h16, int n4) {
    int i = blockIdx.x * blockDim.x + threadIdx.x;
    if (i < n4) {
        float4 v = h[i];
        h16[i * 2 + 0] = __floats2half2_rn(v.x, v.y);
        h16[i * 2 + 1] = __floats2half2_rn(v.z, v.w);
    }
}

// ---------------- embedding sum + LayerNorm (atom path, fp16 out) ----------------
__global__ void embed_ln_kernel(const int* __restrict__ ids,
                                const float* __restrict__ emb,
                                const float* __restrict__ g,
                                const float* __restrict__ bta,
                                __half* __restrict__ out,
                                int F, int V) {
    int n = blockIdx.x;
    int t = threadIdx.x;
    __shared__ int   sid[16];
    __shared__ float shm[16];
    if (t < F) sid[t] = ids[(size_t)n * F + t];
    __syncthreads();

    float x[3];
    #pragma unroll
    for (int j = 0; j < 3; j++) {
        int d = t + j * 256;
        float s = 0.f;
        for (int f = 0; f < F; f++)
            s += emb[((size_t)(f * V + sid[f])) * D + d];
        x[j] = s;
    }
    float s1 = x[0] + x[1] + x[2];
    float s2 = x[0]*x[0] + x[1]*x[1] + x[2]*x[2];
    block_reduce2(s1, s2, shm);
    float mean = s1 * (1.0f / D);
    float var  = s2 * (1.0f / D) - mean * mean;
    float inv  = rsqrtf(var + 1e-5f);
    __half* o = out + (size_t)n * D;
    #pragma unroll
    for (int j = 0; j < 3; j++) {
        int d = t + j * 256;
        o[d] = __float2half_rn((x[j] - mean) * inv * g[d] + bta[d]);
    }
}

// ---------------- bond table embed+LN: one block per code ----------------
__global__ void embed_ln_bond_kernel(const float* __restrict__ emb,
                                     const float* __restrict__ g,
                                     const float* __restrict__ bta,
                                     __half* __restrict__ out) {
    int n = blockIdx.x;
    int t = threadIdx.x;
    __shared__ float shm[16];
    int id0 = (n >> 6) & 7, id1 = (n >> 3) & 7, id2 = n & 7;

    float x[3];
    #pragma unroll
    for (int j = 0; j < 3; j++) {
        int d = t + j * 256;
        x[j] = emb[((size_t)(0 * 8 + id0)) * D + d]
             + emb[((size_t)(1 * 8 + id1)) * D + d]
             + emb[((size_t)(2 * 8 + id2)) * D + d];
    }
    float s1 = x[0] + x[1] + x[2];
    float s2 = x[0]*x[0] + x[1]*x[1] + x[2]*x[2];
    block_reduce2(s1, s2, shm);
    float mean = s1 * (1.0f / D);
    float var  = s2 * (1.0f / D) - mean * mean;
    float inv  = rsqrtf(var + 1e-5f);
    __half* o = out + (size_t)n * D;
    #pragma unroll
    for (int j = 0; j < 3; j++) {
        int d = t + j * 256;
        o[d] = __float2half_rn((x[j] - mean) * inv * g[d] + bta[d]);
    }
}

// ---------------- CSR edge aggregation: a16[n] = fp16(h[n] + sum relu(h16[src]+etab[code])) ----------------
__global__ void edge_agg_kernel(const int* __restrict__ rowstart,
                                const int* __restrict__ srcs,
                                const int* __restrict__ codes,
                                const float* __restrict__ hcur,
                                const __half* __restrict__ h16,
                                const __half* __restrict__ etab,
                                __half* __restrict__ a16) {
    int n = blockIdx.x;
    int t = threadIdx.x;  // 192 threads * 4 floats = 768
    float4 z = ((const float4*)(hcur + (size_t)n * D))[t];
    int beg = __ldg(rowstart + n);
    int end = __ldg(rowstart + n + 1);
    for (int p = beg; p < end; p++) {
        int src = __ldg(srcs + p);
        int c   = __ldg(codes + p);
        const __half2* hp = (const __half2*)(h16 + (size_t)src * D) + t * 2;
        const __half2* ep = (const __half2*)(etab + (size_t)c * D) + t * 2;
        float2 h0 = __half22float2(hp[0]);
        float2 h1 = __half22float2(hp[1]);
        float2 e0 = __half22float2(ep[0]);
        float2 e1 = __half22float2(ep[1]);
        z.x += fmaxf(h0.x + e0.x, 0.f);
        z.y += fmaxf(h0.y + e0.y, 0.f);
        z.z += fmaxf(h1.x + e1.x, 0.f);
        z.w += fmaxf(h1.y + e1.y, 0.f);
    }
    __half2* o = (__half2*)(a16 + (size_t)n * D) + t * 2;
    o[0] = __floats2half2_rn(z.x, z.y);
    o[1] = __floats2half2_rn(z.z, z.w);
}

// ---------------- fused gelu + residual + LayerNorm (+ h16 mirror) ----------------
__global__ void ln_res_kernel(const float* __restrict__ z,
                              const float* __restrict__ hin,
                              const float* __restrict__ g,
                              const float* __restrict__ bta,
                              float* __restrict__ out,
                              __half* __restrict__ h16) {
    int n = blockIdx.x;
    int t = threadIdx.x;
    __shared__ float shm[16];
    float x[3];
    #pragma unroll
    for (int j = 0; j < 3; j++) {
        int d = t + j * 256;
        x[j] = gelu_f(z[(size_t)n * D + d]) + hin[(size_t)n * D + d];
    }
    float s1 = x[0] + x[1] + x[2];
    float s2 = x[0]*x[0] + x[1]*x[1] + x[2]*x[2];
    block_reduce2(s1, s2, shm);
    float mean = s1 * (1.0f / D);
    float var  = s2 * (1.0f / D) - mean * mean;
    float inv  = rsqrtf(var + 1e-5f);
    #pragma unroll
    for (int j = 0; j < 3; j++) {
        int d = t + j * 256;
        float r = (x[j] - mean) * inv * g[d] + bta[d];
        out[(size_t)n * D + d] = r;
        if (h16) h16[(size_t)n * D + d] = __float2half_rn(r);
    }
}

// ---------------- host orchestration ----------------
extern "C" void kernel_launch(void* const* d_in, const int* in_sizes, int n_in,
                              void* d_out, int out_size) {
    const int*   x          = (const int*)d_in[0];
    const int*   edge_attr  = (const int*)d_in[1];
    const int*   edge_index = (const int*)d_in[2];
    const float* atom_emb   = (const float*)d_in[3];
    const float* atom_ln_g  = (const float*)d_in[4];
    const float* atom_ln_b  = (const float*)d_in[5];
    const float* atom_w1    = (const float*)d_in[6];
    const float* atom_b1    = (const float*)d_in[7];
    const float* atom_w2    = (const float*)d_in[8];
    const float* atom_b2    = (const float*)d_in[9];
    const float* bond_emb   = (const float*)d_in[10];
    const float* bond_ln_g  = (const float*)d_in[11];
    const float* bond_ln_b  = (const float*)d_in[12];
    const float* bond_w1    = (const float*)d_in[13];
    const float* bond_b1    = (const float*)d_in[14];
    const float* bond_w2    = (const float*)d_in[15];
    const float* bond_b2    = (const float*)d_in[16];
    const float* conv_w1    = (const float*)d_in[17];
    const float* conv_b1    = (const float*)d_in[18];
    const float* conv_w2    = (const float*)d_in[19];
    const float* conv_b2    = (const float*)d_in[20];
    const float* ln_g       = (const float*)d_in[21];
    const float* ln_b       = (const float*)d_in[22];
    float* out = (float*)d_out;

    int N = in_sizes[0] / 9;
    int E = in_sizes[1] / 3;
    if (N > MAXN) N = MAXN;
    if (E > MAXE) E = MAXE;

    float *phA, *phB, *pz;
    int *phist, *pcnt, *prow, *psrcs, *pcodes;
    __half *petab, *pbtmp, *ph16, *pa16, *pt16, *pw16;
    cudaGetSymbolAddress((void**)&phA,    g_hA);
    cudaGetSymbolAddress((void**)&phB,    g_hB);
    cudaGetSymbolAddress((void**)&pz,     g_z);
    cudaGetSymbolAddress((void**)&phist,  g_hist);
    cudaGetSymbolAddress((void**)&pcnt,   g_cnt);
    cudaGetSymbolAddress((void**)&prow,   g_rowstart);
    cudaGetSymbolAddress((void**)&psrcs,  g_srcs);
    cudaGetSymbolAddress((void**)&pcodes, g_codes);
    cudaGetSymbolAddress((void**)&petab,  g_etab);
    cudaGetSymbolAddress((void**)&pbtmp,  g_btmp);
    cudaGetSymbolAddress((void**)&ph16,   g_h16);
    cudaGetSymbolAddress((void**)&pa16,   g_a16);
    cudaGetSymbolAddress((void**)&pt16,   g_t16);
    cudaGetSymbolAddress((void**)&pw16,   g_w16);

    cudaFuncSetAttribute(gemm_kernel<0, false>, cudaFuncAttributeMaxDynamicSharedMemorySize, GEMM_SMEM);
    cudaFuncSetAttribute(gemm_kernel<0, true>,  cudaFuncAttributeMaxDynamicSharedMemorySize, GEMM_SMEM);
    cudaFuncSetAttribute(gemm_kernel<1, true>,  cudaFuncAttributeMaxDynamicSharedMemorySize, GEMM_SMEM);
    cudaFuncSetAttribute(gemm_kernel<2, true>,  cudaFuncAttributeMaxDynamicSharedMemorySize, GEMM_SMEM);

    WPtrs wp;
    wp.p[0] = atom_w1; wp.p[1] = atom_w2; wp.p[2] = bond_w1;
    wp.p[3] = bond_w2; wp.p[4] = conv_w1; wp.p[5] = conv_w2;

    auto WT = [&](int i) { return pw16 + (size_t)i * D * D; };
    dim3 gN(D / BN, (N + BM - 1) / BM);
    dim3 gB(D / BN, (NBOND + BM - 1) / BM);

    // launches 0-3
    transpose_all_kernel<<<dim3(D / 32, D / 32, 12), dim3(32, 8)>>>(wp, pw16);      // 0
    zero2_kernel<<<(N + 255) / 256, 256>>>(phist, pcnt, N);                          // 1
    embed_ln_kernel<<<N, 256>>>(x, atom_emb, atom_ln_g, atom_ln_b, pa16, 9, 128);    // 2
    embed_ln_bond_kernel<<<NBOND, 256>>>(bond_emb, bond_ln_g, bond_ln_b, pbtmp);     // 3
    // launches 4-5: atom encoder GEMMs (#5 = full N-GEMM -> ncu)
    gemm_kernel<2, true ><<<gN, GEMM_THREADS, GEMM_SMEM>>>(pa16, WT(0), atom_b1, pt16, N);   // 4
    gemm_kernel<0, false><<<gN, GEMM_THREADS, GEMM_SMEM>>>(pt16, WT(1), atom_b2, phA, N);    // 5

    // CSR build
    hist_kernel<<<(E + 255) / 256, 256>>>(edge_index, phist, E);
    scan_kernel<<<1, 1024>>>(phist, prow, N);
    scatter_kernel<<<(E + 255) / 256, 256>>>(edge_index, edge_attr, prow, pcnt, psrcs, pcodes, E);

    // bond-table encoder GEMMs (512 rows)
    gemm_kernel<2, true ><<<gB, GEMM_THREADS, GEMM_SMEM>>>(pbtmp, WT(2), bond_b1, pbtmp + (size_t)NBOND * D, NBOND);
    gemm_kernel<0, true ><<<gB, GEMM_THREADS, GEMM_SMEM>>>(pbtmp + (size_t)NBOND * D, WT(3), bond_b2, petab, NBOND);

    // h16 = fp16(h)
    int n4 = N * D / 4;
    seed_kernel<<<(n4 + 255) / 256, 256>>>((const float4*)phA, (__half2*)ph16, n4);

    const float* hcur = phA;
    float* hnext = phB;
    for (int l = 0; l < N_LAYERS; l++) {
        // a16[n] = fp16( h[n] + sum_{edges->n} relu(h16[src] + etab[code]) )
        edge_agg_kernel<<<N, 192>>>(prow, psrcs, pcodes, hcur, ph16, petab, pa16);
        // conv MLP
        gemm_kernel<1, true ><<<gN, GEMM_THREADS, GEMM_SMEM>>>(pa16, WT(4 + l), conv_b1 + l * D, pt16, N);
        gemm_kernel<0, false><<<gN, GEMM_THREADS, GEMM_SMEM>>>(pt16, WT(8 + l), conv_b2 + l * D, pz, N);
        // h = LN(gelu(z) + h_in); refresh h16 mirror (except last layer)
        float*  dst = (l == N_LAYERS - 1) ? out : hnext;
        __half* mir = (l == N_LAYERS - 1) ? nullptr : ph16;
        ln_res_kernel<<<N, 256>>>(pz, hcur, ln_g + l * D, ln_b + l * D, dst, mir);

        float* old = (float*)hcur;
        hcur = dst;
        hnext = old;
    }
}

// round 15
// speedup vs baseline: 1.7755x; 1.0614x over previous
#include <cuda_runtime.h>
#include <cuda_fp16.h>
#include <cstdint>
#include <cstddef>

#define D 768
#define N_LAYERS 4
#define MAXN 50000
#define MAXE 100000
#define NBOND 512   // 8^3 distinct edge-attr triples

// ---------------- static scratch (allocation-free rule) ----------------
__device__ float  g_hA [(size_t)MAXN * D];
__device__ float  g_hB [(size_t)MAXN * D];
__device__ float  g_z  [(size_t)MAXN * D];                  // conv-MLP output (fp32)
__device__ int    g_hist[(size_t)MAXN];
__device__ int    g_cnt [(size_t)MAXN];
__device__ int    g_rowstart[(size_t)MAXN + 1];
__device__ int    g_srcs [(size_t)MAXE];
__device__ int    g_codes[(size_t)MAXE];
__device__ __align__(128) __half g_etab[(size_t)NBOND * D]; // bond-type table (fp16)
__device__ __align__(128) __half g_btmp[(size_t)2 * NBOND * D];
__device__ __align__(128) __half g_h16[(size_t)MAXN * D];   // fp16 mirror of h
__device__ __align__(128) __half g_a16[(size_t)MAXN * D];   // GEMM-1 inputs (fp16)
__device__ __align__(128) __half g_t16[(size_t)MAXN * D];   // hidden activations (fp16)
__device__ __align__(128) __half g_w16[(size_t)12 * D * D]; // transposed fp16 weights [n][k]

// ---------------- tiny helpers ----------------
__device__ __forceinline__ float gelu_f(float x) {
    const float k0 = 0.7978845608028654f;
    const float k1 = 0.044715f;
    return 0.5f * x * (1.0f + tanhf(k0 * (x + k1 * x * x * x)));
}
template <int ACT>
__device__ __forceinline__ float actf(float x) {
    if (ACT == 1) return fmaxf(x, 0.0f);
    if (ACT == 2) return gelu_f(x);
    return x;
}
__device__ __forceinline__ void block_reduce2(float& s1, float& s2, float* shm) {
    #pragma unroll
    for (int o = 16; o > 0; o >>= 1) {
        s1 += __shfl_xor_sync(0xffffffffu, s1, o);
        s2 += __shfl_xor_sync(0xffffffffu, s2, o);
    }
    int wid = threadIdx.x >> 5, lane = threadIdx.x & 31;
    if (lane == 0) { shm[wid] = s1; shm[8 + wid] = s2; }
    __syncthreads();
    float a = 0.f, b = 0.f;
    #pragma unroll
    for (int i = 0; i < 8; i++) { a += shm[i]; b += shm[8 + i]; }
    s1 = a; s2 = b;
}

__device__ __forceinline__ void cp_async16(void* s, const void* g) {
    uint32_t sa = (uint32_t)__cvta_generic_to_shared(s);
    asm volatile("cp.async.cg.shared.global [%0], [%1], 16;" :: "r"(sa), "l"(g));
}
__device__ __forceinline__ void ldsm_x4(uint32_t* r, uint32_t addr) {
    asm volatile("ldmatrix.sync.aligned.m8n8.x4.shared.b16 {%0,%1,%2,%3}, [%4];"
                 : "=r"(r[0]), "=r"(r[1]), "=r"(r[2]), "=r"(r[3]) : "r"(addr));
}
__device__ __forceinline__ void mma_f16(float* c, const uint32_t* a, uint32_t b0, uint32_t b1) {
    asm volatile(
        "mma.sync.aligned.m16n8k16.row.col.f32.f16.f16.f32 "
        "{%0,%1,%2,%3},{%4,%5,%6,%7},{%8,%9},{%0,%1,%2,%3};"
        : "+f"(c[0]), "+f"(c[1]), "+f"(c[2]), "+f"(c[3])
        : "r"(a[0]), "r"(a[1]), "r"(a[2]), "r"(a[3]), "r"(b0), "r"(b1));
}

// ---------------- fp16 tensor-core GEMM (2 CTAs/SM, BK=64, 3-stage) ----------------
#define BM 128
#define BN 128
#define BK 64
#define NT (D / BK)                      // 12 iterations (half the barrier count)
#define NSTAGE 3
#define SROW 144                         // 64 halves (128B) + 16B pad -> LDSM conflict-free
#define A_BYTES (BM * SROW)              // 18432
#define STAGE_BYTES (A_BYTES + BN * SROW)  // 36864
#define GEMM_THREADS 256
#define GEMM_SMEM (NSTAGE * STAGE_BYTES)   // 110592 (2 CTAs = 221184 <= 228KB)

template <int ACT, bool HOUT>
__global__ void __launch_bounds__(GEMM_THREADS, 2)
gemm_kernel(const __half* __restrict__ A, const __half* __restrict__ Wt,
            const float* __restrict__ bias, void* __restrict__ Cv, int M)
{
    extern __shared__ char smem[];
    const int t  = threadIdx.x;
    const int m0 = blockIdx.y * BM;
    const int n0 = blockIdx.x * BN;
    const uint32_t sbu = (uint32_t)__cvta_generic_to_shared(smem);

    auto load_stage = [&](int s, int kt) {
        char* abuf = smem + s * STAGE_BYTES;
        char* bbuf = abuf + A_BYTES;
        #pragma unroll
        for (int i = 0; i < 4; i++) {   // A: 128 rows x 128B = 1024 chunks
            int q = t + i * GEMM_THREADS;
            int row = q >> 3, c = q & 7;
            int m = m0 + row; m = (m < M) ? m : (M - 1);
            cp_async16(abuf + row * SROW + c * 16, A + (size_t)m * D + kt * BK + c * 8);
        }
        #pragma unroll
        for (int i = 0; i < 4; i++) {   // B: 128 rows x 128B = 1024 chunks
            int q = t + i * GEMM_THREADS;
            int row = q >> 3, c = q & 7;
            cp_async16(bbuf + row * SROW + c * 16, Wt + (size_t)(n0 + row) * D + kt * BK + c * 8);
        }
    };

    float acc[2][8][4];
    #pragma unroll
    for (int i = 0; i < 2; i++)
        #pragma unroll
        for (int j = 0; j < 8; j++)
            #pragma unroll
            for (int k = 0; k < 4; k++) acc[i][j][k] = 0.f;

    #pragma unroll
    for (int s = 0; s < NSTAGE; s++) {
        load_stage(s, s);
        asm volatile("cp.async.commit_group;" ::: "memory");
    }

    const int lane = t & 31, wid = t >> 5;
    const int wm = (wid & 3) * 32;      // 4 warps over M(128)
    const int wn = (wid >> 2) * 64;     // 2 warps over N(128)
    const int gr = lane >> 2, tig = lane & 3;

    const uint32_t a_off0 = (uint32_t)((wm + (lane & 15)) * SROW + (lane >> 4) * 16);
    const uint32_t b_off0 = (uint32_t)((wn + (lane & 7) + ((lane >> 4) & 1) * 8) * SROW
                                       + ((lane >> 3) & 1) * 16);

    for (int kt = 0; kt < NT; ++kt) {
        const int s = kt % NSTAGE;
        asm volatile("cp.async.wait_group %0;" :: "n"(NSTAGE - 1) : "memory");
        __syncthreads();
        const uint32_t sa = sbu + s * STAGE_BYTES;
        const uint32_t sb = sa + A_BYTES;
        #pragma unroll
        for (int kc = 0; kc < 4; kc++) {           // four k16 sub-tiles (BK=64)
            uint32_t af[2][4];
            #pragma unroll
            for (int mi = 0; mi < 2; mi++)
                ldsm_x4(af[mi], sa + a_off0 + mi * 16 * SROW + kc * 32);
            #pragma unroll
            for (int jp = 0; jp < 4; jp++) {
                uint32_t bf[4];
                ldsm_x4(bf, sb + b_off0 + jp * 16 * SROW + kc * 32);
                mma_f16(acc[0][jp * 2 + 0], af[0], bf[0], bf[1]);
                mma_f16(acc[1][jp * 2 + 0], af[1], bf[0], bf[1]);
                mma_f16(acc[0][jp * 2 + 1], af[0], bf[2], bf[3]);
                mma_f16(acc[1][jp * 2 + 1], af[1], bf[2], bf[3]);
            }
        }
        __syncthreads();
        if (kt + NSTAGE < NT) load_stage(s, kt + NSTAGE);
        asm volatile("cp.async.commit_group;" ::: "memory");
    }

    #pragma unroll
    for (int mi = 0; mi < 2; mi++) {
        int row0 = m0 + wm + mi * 16 + gr;
        #pragma unroll
        for (int ni = 0; ni < 8; ni++) {
            int col = n0 + wn + ni * 8 + tig * 2;
            float bv0 = __ldg(bias + col), bv1 = __ldg(bias + col + 1);
            float v0 = actf<ACT>(acc[mi][ni][0] + bv0);
            float v1 = actf<ACT>(acc[mi][ni][1] + bv1);
            float v2 = actf<ACT>(acc[mi][ni][2] + bv0);
            float v3 = actf<ACT>(acc[mi][ni][3] + bv1);
            if (HOUT) {
                __half* C = (__half*)Cv;
                if (row0 < M)
                    *(__half2*)(C + (size_t)row0 * D + col) = __floats2half2_rn(v0, v1);
                if (row0 + 8 < M)
                    *(__half2*)(C + (size_t)(row0 + 8) * D + col) = __floats2half2_rn(v2, v3);
            } else {
                float* C = (float*)Cv;
                if (row0 < M)
                    *(float2*)(C + (size_t)row0 * D + col) = make_float2(v0, v1);
                if (row0 + 8 < M)
                    *(float2*)(C + (size_t)(row0 + 8) * D + col) = make_float2(v2, v3);
            }
        }
    }
}

// ---------------- weight transpose + fp16 convert (one launch) ----------------
struct WPtrs { const float* p[6]; };
__global__ void transpose_all_kernel(WPtrs w, __half* __restrict__ wt) {
    int mat = blockIdx.z;
    const float* W = (mat < 4) ? w.p[mat]
                   : (mat < 8) ? w.p[4] + (size_t)(mat - 4) * D * D
                               : w.p[5] + (size_t)(mat - 8) * D * D;
    __half* Wt = wt + (size_t)mat * D * D;
    __shared__ float tile[32][33];
    int bx = blockIdx.x * 32;
    int by = blockIdx.y * 32;
    int tx = threadIdx.x, ty = threadIdx.y;
    #pragma unroll
    for (int j = 0; j < 32; j += 8)
        tile[ty + j][tx] = W[(size_t)(by + ty + j) * D + bx + tx];
    __syncthreads();
    #pragma unroll
    for (int j = 0; j < 32; j += 8)
        Wt[(size_t)(bx + ty + j) * D + by + tx] = __float2half_rn(tile[tx][ty + j]);
}

// ---------------- CSR build ----------------
__global__ void zero2_kernel(int* __restrict__ a, int* __restrict__ b, int n) {
    int i = blockIdx.x * blockDim.x + threadIdx.x;
    if (i < n) { a[i] = 0; b[i] = 0; }
}
__global__ void hist_kernel(const int* __restrict__ ei, int* __restrict__ hist, int E) {
    int i = blockIdx.x * blockDim.x + threadIdx.x;
    if (i < E) atomicAdd(hist + ei[E + i], 1);
}
// single-block exclusive scan of hist[0..n) -> rowstart[0..n], 1024 threads
__global__ void scan_kernel(const int* __restrict__ hist, int* __restrict__ rowstart, int n) {
    __shared__ int wsum[32];
    __shared__ int s_carry;
    int t = threadIdx.x;
    int lane = t & 31, w = t >> 5;
    if (t == 0) s_carry = 0;
    __syncthreads();
    for (int base = 0; base < n; base += 1024) {
        int idx = base + t;
        int v = (idx < n) ? hist[idx] : 0;
        int x = v;
        #pragma unroll
        for (int o = 1; o < 32; o <<= 1) {
            int y = __shfl_up_sync(0xffffffffu, x, o);
            if (lane >= o) x += y;
        }
        if (lane == 31) wsum[w] = x;
        __syncthreads();
        if (w == 0) {
            int s = wsum[lane];
            #pragma unroll
            for (int o = 1; o < 32; o <<= 1) {
                int y = __shfl_up_sync(0xffffffffu, s, o);
                if (lane >= o) s += y;
            }
            wsum[lane] = s;
        }
        __syncthreads();
        int incl = x + (w > 0 ? wsum[w - 1] : 0);
        int carry = s_carry;
        if (idx < n) rowstart[idx] = carry + incl - v;
        __syncthreads();
        if (t == 0) s_carry = carry + wsum[31];
        __syncthreads();
    }
    if (t == 0) rowstart[n] = s_carry;
}
__global__ void scatter_kernel(const int* __restrict__ ei, const int* __restrict__ ea,
                               const int* __restrict__ rowstart, int* __restrict__ cnt,
                               int* __restrict__ srcs, int* __restrict__ codes, int E) {
    int i = blockIdx.x * blockDim.x + threadIdx.x;
    if (i < E) {
        int dst = ei[E + i];
        int pos = rowstart[dst] + atomicAdd(cnt + dst, 1);
        srcs[pos]  = ei[i];
        codes[pos] = ea[i * 3] * 64 + ea[i * 3 + 1] * 8 + ea[i * 3 + 2];
    }
}

// ---------------- seed: h16 = fp16(h) ----------------
__global__ void seed_kernel(const float4* __restrict__ h, __half2* __restrict__ h16, int n4) {
    int i = blockIdx.x * blockDim.x + threadIdx.x;
    if (i < n4) {
        float4 v = h[i];
        h16[i * 2 + 0] = __floats2half2_rn(v.x, v.y);
        h16[i * 2 + 1] = __floats2half2_rn(v.z, v.w);
    }
}

// ---------------- embedding sum + LayerNorm (atom path, fp16 out) ----------------
__global__ void embed_ln_kernel(const int* __restrict__ ids,
                                const float* __restrict__ emb,
                                const float* __restrict__ g,
                                const float* __restrict__ bta,
                                __half* __restrict__ out,
                                int F, int V) {
    int n = blockIdx.x;
    int t = threadIdx.x;
    __shared__ int   sid[16];
    __shared__ float shm[16];
    if (t < F) sid[t] = ids[(size_t)n * F + t];
    __syncthreads();

    float x[3];
    #pragma unroll
    for (int j = 0; j < 3; j++) {
        int d = t + j * 256;
        float s = 0.f;
        for (int f = 0; f < F; f++)
            s += emb[((size_t)(f * V + sid[f])) * D + d];
        x[j] = s;
    }
    float s1 = x[0] + x[1] + x[2];
    float s2 = x[0]*x[0] + x[1]*x[1] + x[2]*x[2];
    block_reduce2(s1, s2, shm);
    float mean = s1 * (1.0f / D);
    float var  = s2 * (1.0f / D) - mean * mean;
    float inv  = rsqrtf(var + 1e-5f);
    __half* o = out + (size_t)n * D;
    #pragma unroll
    for (int j = 0; j < 3; j++) {
        int d = t + j * 256;
        o[d] = __float2half_rn((x[j] - mean) * inv * g[d] + bta[d]);
    }
}

// ---------------- bond table embed+LN: one block per code ----------------
__global__ void embed_ln_bond_kernel(const float* __restrict__ emb,
                                     const float* __restrict__ g,
                                     const float* __restrict__ bta,
                                     __half* __restrict__ out) {
    int n = blockIdx.x;
    int t = threadIdx.x;
    __shared__ float shm[16];
    int id0 = (n >> 6) & 7, id1 = (n >> 3) & 7, id2 = n & 7;

    float x[3];
    #pragma unroll
    for (int j = 0; j < 3; j++) {
        int d = t + j * 256;
        x[j] = emb[((size_t)(0 * 8 + id0)) * D + d]
             + emb[((size_t)(1 * 8 + id1)) * D + d]
             + emb[((size_t)(2 * 8 + id2)) * D + d];
    }
    float s1 = x[0] + x[1] + x[2];
    float s2 = x[0]*x[0] + x[1]*x[1] + x[2]*x[2];
    block_reduce2(s1, s2, shm);
    float mean = s1 * (1.0f / D);
    float var  = s2 * (1.0f / D) - mean * mean;
    float inv  = rsqrtf(var + 1e-5f);
    __half* o = out + (size_t)n * D;
    #pragma unroll
    for (int j = 0; j < 3; j++) {
        int d = t + j * 256;
        o[d] = __float2half_rn((x[j] - mean) * inv * g[d] + bta[d]);
    }
}

// ---------------- CSR edge aggregation: a16[n] = fp16(h[n] + sum relu(h16[src]+etab[code])) ----------------
__global__ void edge_agg_kernel(const int* __restrict__ rowstart,
                                const int* __restrict__ srcs,
                                const int* __restrict__ codes,
                                const float* __restrict__ hcur,
                                const __half* __restrict__ h16,
                                const __half* __restrict__ etab,
                                __half* __restrict__ a16) {
    int n = blockIdx.x;
    int t = threadIdx.x;  // 192 threads * 4 floats = 768
    float4 z = ((const float4*)(hcur + (size_t)n * D))[t];
    int beg = __ldg(rowstart + n);
    int end = __ldg(rowstart + n + 1);
    for (int p = beg; p < end; p++) {
        int src = __ldg(srcs + p);
        int c   = __ldg(codes + p);
        const __half2* hp = (const __half2*)(h16 + (size_t)src * D) + t * 2;
        const __half2* ep = (const __half2*)(etab + (size_t)c * D) + t * 2;
        float2 h0 = __half22float2(hp[0]);
        float2 h1 = __half22float2(hp[1]);
        float2 e0 = __half22float2(ep[0]);
        float2 e1 = __half22float2(ep[1]);
        z.x += fmaxf(h0.x + e0.x, 0.f);
        z.y += fmaxf(h0.y + e0.y, 0.f);
        z.z += fmaxf(h1.x + e1.x, 0.f);
        z.w += fmaxf(h1.y + e1.y, 0.f);
    }
    __half2* o = (__half2*)(a16 + (size_t)n * D) + t * 2;
    o[0] = __floats2half2_rn(z.x, z.y);
    o[1] = __floats2half2_rn(z.z, z.w);
}

// ---------------- fused gelu + residual + LayerNorm (+ h16 mirror) ----------------
__global__ void ln_res_kernel(const float* __restrict__ z,
                              const float* __restrict__ hin,
                              const float* __restrict__ g,
                              const float* __restrict__ bta,
                              float* __restrict__ out,
                              __half* __restrict__ h16) {
    int n = blockIdx.x;
    int t = threadIdx.x;
    __shared__ float shm[16];
    float x[3];
    #pragma unroll
    for (int j = 0; j < 3; j++) {
        int d = t + j * 256;
        x[j] = gelu_f(z[(size_t)n * D + d]) + hin[(size_t)n * D + d];
    }
    float s1 = x[0] + x[1] + x[2];
    float s2 = x[0]*x[0] + x[1]*x[1] + x[2]*x[2];
    block_reduce2(s1, s2, shm);
    float mean = s1 * (1.0f / D);
    float var  = s2 * (1.0f / D) - mean * mean;
    float inv  = rsqrtf(var + 1e-5f);
    #pragma unroll
    for (int j = 0; j < 3; j++) {
        int d = t + j * 256;
        float r = (x[j] - mean) * inv * g[d] + bta[d];
        out[(size_t)n * D + d] = r;
        if (h16) h16[(size_t)n * D + d] = __float2half_rn(r);
    }
}

// ---------------- host orchestration ----------------
extern "C" void kernel_launch(void* const* d_in, const int* in_sizes, int n_in,
                              void* d_out, int out_size) {
    const int*   x          = (const int*)d_in[0];
    const int*   edge_attr  = (const int*)d_in[1];
    const int*   edge_index = (const int*)d_in[2];
    const float* atom_emb   = (const float*)d_in[3];
    const float* atom_ln_g  = (const float*)d_in[4];
    const float* atom_ln_b  = (const float*)d_in[5];
    const float* atom_w1    = (const float*)d_in[6];
    const float* atom_b1    = (const float*)d_in[7];
    const float* atom_w2    = (const float*)d_in[8];
    const float* atom_b2    = (const float*)d_in[9];
    const float* bond_emb   = (const float*)d_in[10];
    const float* bond_ln_g  = (const float*)d_in[11];
    const float* bond_ln_b  = (const float*)d_in[12];
    const float* bond_w1    = (const float*)d_in[13];
    const float* bond_b1    = (const float*)d_in[14];
    const float* bond_w2    = (const float*)d_in[15];
    const float* bond_b2    = (const float*)d_in[16];
    const float* conv_w1    = (const float*)d_in[17];
    const float* conv_b1    = (const float*)d_in[18];
    const float* conv_w2    = (const float*)d_in[19];
    const float* conv_b2    = (const float*)d_in[20];
    const float* ln_g       = (const float*)d_in[21];
    const float* ln_b       = (const float*)d_in[22];
    float* out = (float*)d_out;

    int N = in_sizes[0] / 9;
    int E = in_sizes[1] / 3;
    if (N > MAXN) N = MAXN;
    if (E > MAXE) E = MAXE;

    float *phA, *phB, *pz;
    int *phist, *pcnt, *prow, *psrcs, *pcodes;
    __half *petab, *pbtmp, *ph16, *pa16, *pt16, *pw16;
    cudaGetSymbolAddress((void**)&phA,    g_hA);
    cudaGetSymbolAddress((void**)&phB,    g_hB);
    cudaGetSymbolAddress((void**)&pz,     g_z);
    cudaGetSymbolAddress((void**)&phist,  g_hist);
    cudaGetSymbolAddress((void**)&pcnt,   g_cnt);
    cudaGetSymbolAddress((void**)&prow,   g_rowstart);
    cudaGetSymbolAddress((void**)&psrcs,  g_srcs);
    cudaGetSymbolAddress((void**)&pcodes, g_codes);
    cudaGetSymbolAddress((void**)&petab,  g_etab);
    cudaGetSymbolAddress((void**)&pbtmp,  g_btmp);
    cudaGetSymbolAddress((void**)&ph16,   g_h16);
    cudaGetSymbolAddress((void**)&pa16,   g_a16);
    cudaGetSymbolAddress((void**)&pt16,   g_t16);
    cudaGetSymbolAddress((void**)&pw16,   g_w16);

    cudaFuncSetAttribute(gemm_kernel<0, false>, cudaFuncAttributeMaxDynamicSharedMemorySize, GEMM_SMEM);
    cudaFuncSetAttribute(gemm_kernel<0, true>,  cudaFuncAttributeMaxDynamicSharedMemorySize, GEMM_SMEM);
    cudaFuncSetAttribute(gemm_kernel<1, true>,  cudaFuncAttributeMaxDynamicSharedMemorySize, GEMM_SMEM);
    cudaFuncSetAttribute(gemm_kernel<2, true>,  cudaFuncAttributeMaxDynamicSharedMemorySize, GEMM_SMEM);

    WPtrs wp;
    wp.p[0] = atom_w1; wp.p[1] = atom_w2; wp.p[2] = bond_w1;
    wp.p[3] = bond_w2; wp.p[4] = conv_w1; wp.p[5] = conv_w2;

    auto WT = [&](int i) { return pw16 + (size_t)i * D * D; };
    dim3 gN(D / BN, (N + BM - 1) / BM);
    dim3 gB(D / BN, (NBOND + BM - 1) / BM);

    // launches 0-3
    transpose_all_kernel<<<dim3(D / 32, D / 32, 12), dim3(32, 8)>>>(wp, pw16);      // 0
    zero2_kernel<<<(N + 255) / 256, 256>>>(phist, pcnt, N);                          // 1
    embed_ln_kernel<<<N, 256>>>(x, atom_emb, atom_ln_g, atom_ln_b, pa16, 9, 128);    // 2
    embed_ln_bond_kernel<<<NBOND, 256>>>(bond_emb, bond_ln_g, bond_ln_b, pbtmp);     // 3
    // launches 4-5: atom encoder GEMMs (#5 = full N-GEMM -> ncu)
    gemm_kernel<2, true ><<<gN, GEMM_THREADS, GEMM_SMEM>>>(pa16, WT(0), atom_b1, pt16, N);   // 4
    gemm_kernel<0, false><<<gN, GEMM_THREADS, GEMM_SMEM>>>(pt16, WT(1), atom_b2, phA, N);    // 5

    // CSR build
    hist_kernel<<<(E + 255) / 256, 256>>>(edge_index, phist, E);
    scan_kernel<<<1, 1024>>>(phist, prow, N);
    scatter_kernel<<<(E + 255) / 256, 256>>>(edge_index, edge_attr, prow, pcnt, psrcs, pcodes, E);

    // bond-table encoder GEMMs (512 rows)
    gemm_kernel<2, true ><<<gB, GEMM_THREADS, GEMM_SMEM>>>(pbtmp, WT(2), bond_b1, pbtmp + (size_t)NBOND * D, NBOND);
    gemm_kernel<0, true ><<<gB, GEMM_THREADS, GEMM_SMEM>>>(pbtmp + (size_t)NBOND * D, WT(3), bond_b2, petab, NBOND);

    // h16 = fp16(h)
    int n4 = N * D / 4;
    seed_kernel<<<(n4 + 255) / 256, 256>>>((const float4*)phA, (__half2*)ph16, n4);

    const float* hcur = phA;
    float* hnext = phB;
    for (int l = 0; l < N_LAYERS; l++) {
        // a16[n] = fp16( h[n] + sum_{edges->n} relu(h16[src] + etab[code]) )
        edge_agg_kernel<<<N, 192>>>(prow, psrcs, pcodes, hcur, ph16, petab, pa16);
        // conv MLP
        gemm_kernel<1, true ><<<gN, GEMM_THREADS, GEMM_SMEM>>>(pa16, WT(4 + l), conv_b1 + l * D, pt16, N);
        gemm_kernel<0, false><<<gN, GEMM_THREADS, GEMM_SMEM>>>(pt16, WT(8 + l), conv_b2 + l * D, pz, N);
        // h = LN(gelu(z) + h_in); refresh h16 mirror (except last layer)
        float*  dst = (l == N_LAYERS - 1) ? out : hnext;
        __half* mir = (l == N_LAYERS - 1) ? nullptr : ph16;
        ln_res_kernel<<<N, 256>>>(pz, hcur, ln_g + l * D, ln_b + l * D, dst, mir);

        float* old = (float*)hcur;
        hcur = dst;
        hnext = old;
    }
}

// round 16
// speedup vs baseline: 1.8075x; 1.0180x over previous
#include <cuda_runtime.h>
#include <cuda_fp16.h>
#include <cstdint>
#include <cstddef>

#define D 768
#define N_LAYERS 4
#define MAXN 50000
#define MAXE 100000
#define NBOND 512   // 8^3 distinct edge-attr triples

// ---------------- static scratch (allocation-free rule) ----------------
__device__ float  g_hA [(size_t)MAXN * D];
__device__ float  g_hB [(size_t)MAXN * D];
__device__ float  g_z  [(size_t)MAXN * D];                  // conv-MLP output (fp32)
__device__ int    g_hist[(size_t)MAXN];
__device__ int    g_cnt [(size_t)MAXN];
__device__ int    g_rowstart[(size_t)MAXN + 1];
__device__ int    g_srcs [(size_t)MAXE];
__device__ int    g_codes[(size_t)MAXE];
__device__ __align__(128) __half g_etab[(size_t)NBOND * D]; // bond-type table (fp16)
__device__ __align__(128) __half g_btmp[(size_t)2 * NBOND * D];
__device__ __align__(128) __half g_h16[(size_t)MAXN * D];   // fp16 mirror of h
__device__ __align__(128) __half g_a16[(size_t)MAXN * D];   // GEMM-1 inputs (fp16)
__device__ __align__(128) __half g_t16[(size_t)MAXN * D];   // hidden activations (fp16)
__device__ __align__(128) __half g_w16[(size_t)12 * D * D]; // transposed fp16 weights [n][k]
__device__ __align__(128) __half g_aemb16[(size_t)9 * 128 * D]; // fp16 atom embedding table

// ---------------- tiny helpers ----------------
__device__ __forceinline__ float gelu_f(float x) {
    const float k0 = 0.7978845608028654f;
    const float k1 = 0.044715f;
    return 0.5f * x * (1.0f + tanhf(k0 * (x + k1 * x * x * x)));
}
template <int ACT>
__device__ __forceinline__ float actf(float x) {
    if (ACT == 1) return fmaxf(x, 0.0f);
    if (ACT == 2) return gelu_f(x);
    return x;
}
__device__ __forceinline__ void block_reduce2(float& s1, float& s2, float* shm) {
    #pragma unroll
    for (int o = 16; o > 0; o >>= 1) {
        s1 += __shfl_xor_sync(0xffffffffu, s1, o);
        s2 += __shfl_xor_sync(0xffffffffu, s2, o);
    }
    int wid = threadIdx.x >> 5, lane = threadIdx.x & 31;
    if (lane == 0) { shm[wid] = s1; shm[8 + wid] = s2; }
    __syncthreads();
    float a = 0.f, b = 0.f;
    #pragma unroll
    for (int i = 0; i < 8; i++) { a += shm[i]; b += shm[8 + i]; }
    s1 = a; s2 = b;
}

__device__ __forceinline__ void cp_async16(void* s, const void* g) {
    uint32_t sa = (uint32_t)__cvta_generic_to_shared(s);
    asm volatile("cp.async.cg.shared.global [%0], [%1], 16;" :: "r"(sa), "l"(g));
}
__device__ __forceinline__ void ldsm_x4(uint32_t* r, uint32_t addr) {
    asm volatile("ldmatrix.sync.aligned.m8n8.x4.shared.b16 {%0,%1,%2,%3}, [%4];"
                 : "=r"(r[0]), "=r"(r[1]), "=r"(r[2]), "=r"(r[3]) : "r"(addr));
}
__device__ __forceinline__ void mma_f16(float* c, const uint32_t* a, uint32_t b0, uint32_t b1) {
    asm volatile(
        "mma.sync.aligned.m16n8k16.row.col.f32.f16.f16.f32 "
        "{%0,%1,%2,%3},{%4,%5,%6,%7},{%8,%9},{%0,%1,%2,%3};"
        : "+f"(c[0]), "+f"(c[1]), "+f"(c[2]), "+f"(c[3])
        : "r"(a[0]), "r"(a[1]), "r"(a[2]), "r"(a[3]), "r"(b0), "r"(b1));
}

// ---------------- fp16 tensor-core GEMM (2 CTAs/SM, BK=64, 3-stage) ----------------
#define BM 128
#define BN 128
#define BK 64
#define NT (D / BK)                      // 12 iterations
#define NSTAGE 3
#define SROW 144                         // 64 halves (128B) + 16B pad -> LDSM conflict-free
#define A_BYTES (BM * SROW)              // 18432
#define STAGE_BYTES (A_BYTES + BN * SROW)  // 36864
#define GEMM_THREADS 256
#define GEMM_SMEM (NSTAGE * STAGE_BYTES)   // 110592 (2 CTAs = 221184 <= 228KB)

// HOUT: fp16 C output. mirror (optional, HOUT=false only): also write fp16 copy of C.
template <int ACT, bool HOUT>
__global__ void __launch_bounds__(GEMM_THREADS, 2)
gemm_kernel(const __half* __restrict__ A, const __half* __restrict__ Wt,
            const float* __restrict__ bias, void* __restrict__ Cv, int M,
            __half* __restrict__ mirror)
{
    extern __shared__ char smem[];
    const int t  = threadIdx.x;
    const int m0 = blockIdx.y * BM;
    const int n0 = blockIdx.x * BN;
    const uint32_t sbu = (uint32_t)__cvta_generic_to_shared(smem);

    auto load_stage = [&](int s, int kt) {
        char* abuf = smem + s * STAGE_BYTES;
        char* bbuf = abuf + A_BYTES;
        #pragma unroll
        for (int i = 0; i < 4; i++) {   // A: 128 rows x 128B
            int q = t + i * GEMM_THREADS;
            int row = q >> 3, c = q & 7;
            int m = m0 + row; m = (m < M) ? m : (M - 1);
            cp_async16(abuf + row * SROW + c * 16, A + (size_t)m * D + kt * BK + c * 8);
        }
        #pragma unroll
        for (int i = 0; i < 4; i++) {   // B: 128 rows x 128B
            int q = t + i * GEMM_THREADS;
            int row = q >> 3, c = q & 7;
            cp_async16(bbuf + row * SROW + c * 16, Wt + (size_t)(n0 + row) * D + kt * BK + c * 8);
        }
    };

    float acc[2][8][4];
    #pragma unroll
    for (int i = 0; i < 2; i++)
        #pragma unroll
        for (int j = 0; j < 8; j++)
            #pragma unroll
            for (int k = 0; k < 4; k++) acc[i][j][k] = 0.f;

    #pragma unroll
    for (int s = 0; s < NSTAGE; s++) {
        load_stage(s, s);
        asm volatile("cp.async.commit_group;" ::: "memory");
    }

    const int lane = t & 31, wid = t >> 5;
    const int wm = (wid & 3) * 32;
    const int wn = (wid >> 2) * 64;
    const int gr = lane >> 2, tig = lane & 3;

    const uint32_t a_off0 = (uint32_t)((wm + (lane & 15)) * SROW + (lane >> 4) * 16);
    const uint32_t b_off0 = (uint32_t)((wn + (lane & 7) + ((lane >> 4) & 1) * 8) * SROW
                                       + ((lane >> 3) & 1) * 16);

    for (int kt = 0; kt < NT; ++kt) {
        const int s = kt % NSTAGE;
        asm volatile("cp.async.wait_group %0;" :: "n"(NSTAGE - 1) : "memory");
        __syncthreads();
        const uint32_t sa = sbu + s * STAGE_BYTES;
        const uint32_t sb = sa + A_BYTES;
        #pragma unroll
        for (int kc = 0; kc < 4; kc++) {
            uint32_t af[2][4];
            #pragma unroll
            for (int mi = 0; mi < 2; mi++)
                ldsm_x4(af[mi], sa + a_off0 + mi * 16 * SROW + kc * 32);
            #pragma unroll
            for (int jp = 0; jp < 4; jp++) {
                uint32_t bf[4];
                ldsm_x4(bf, sb + b_off0 + jp * 16 * SROW + kc * 32);
                mma_f16(acc[0][jp * 2 + 0], af[0], bf[0], bf[1]);
                mma_f16(acc[1][jp * 2 + 0], af[1], bf[0], bf[1]);
                mma_f16(acc[0][jp * 2 + 1], af[0], bf[2], bf[3]);
                mma_f16(acc[1][jp * 2 + 1], af[1], bf[2], bf[3]);
            }
        }
        __syncthreads();
        if (kt + NSTAGE < NT) load_stage(s, kt + NSTAGE);
        asm volatile("cp.async.commit_group;" ::: "memory");
    }

    #pragma unroll
    for (int mi = 0; mi < 2; mi++) {
        int row0 = m0 + wm + mi * 16 + gr;
        #pragma unroll
        for (int ni = 0; ni < 8; ni++) {
            int col = n0 + wn + ni * 8 + tig * 2;
            float bv0 = __ldg(bias + col), bv1 = __ldg(bias + col + 1);
            float v0 = actf<ACT>(acc[mi][ni][0] + bv0);
            float v1 = actf<ACT>(acc[mi][ni][1] + bv1);
            float v2 = actf<ACT>(acc[mi][ni][2] + bv0);
            float v3 = actf<ACT>(acc[mi][ni][3] + bv1);
            if (HOUT) {
                __half* C = (__half*)Cv;
                if (row0 < M)
                    *(__half2*)(C + (size_t)row0 * D + col) = __floats2half2_rn(v0, v1);
                if (row0 + 8 < M)
                    *(__half2*)(C + (size_t)(row0 + 8) * D + col) = __floats2half2_rn(v2, v3);
            } else {
                float* C = (float*)Cv;
                if (row0 < M) {
                    *(float2*)(C + (size_t)row0 * D + col) = make_float2(v0, v1);
                    if (mirror)
                        *(__half2*)(mirror + (size_t)row0 * D + col) = __floats2half2_rn(v0, v1);
                }
                if (row0 + 8 < M) {
                    *(float2*)(C + (size_t)(row0 + 8) * D + col) = make_float2(v2, v3);
                    if (mirror)
                        *(__half2*)(mirror + (size_t)(row0 + 8) * D + col) = __floats2half2_rn(v2, v3);
                }
            }
        }
    }
}

// ---------------- weight transpose + fp16 convert (one launch) ----------------
struct WPtrs { const float* p[6]; };
__global__ void transpose_all_kernel(WPtrs w, __half* __restrict__ wt) {
    int mat = blockIdx.z;
    const float* W = (mat < 4) ? w.p[mat]
                   : (mat < 8) ? w.p[4] + (size_t)(mat - 4) * D * D
                               : w.p[5] + (size_t)(mat - 8) * D * D;
    __half* Wt = wt + (size_t)mat * D * D;
    __shared__ float tile[32][33];
    int bx = blockIdx.x * 32;
    int by = blockIdx.y * 32;
    int tx = threadIdx.x, ty = threadIdx.y;
    #pragma unroll
    for (int j = 0; j < 32; j += 8)
        tile[ty + j][tx] = W[(size_t)(by + ty + j) * D + bx + tx];
    __syncthreads();
    #pragma unroll
    for (int j = 0; j < 32; j += 8)
        Wt[(size_t)(bx + ty + j) * D + by + tx] = __float2half_rn(tile[tx][ty + j]);
}

// ---------------- atom embedding table -> fp16 ----------------
__global__ void cvt_emb_kernel(const float4* __restrict__ src, __half2* __restrict__ dst, int n4) {
    int i = blockIdx.x * blockDim.x + threadIdx.x;
    if (i < n4) {
        float4 v = src[i];
        dst[i * 2 + 0] = __floats2half2_rn(v.x, v.y);
        dst[i * 2 + 1] = __floats2half2_rn(v.z, v.w);
    }
}

// ---------------- CSR build ----------------
__global__ void zero2_kernel(int* __restrict__ a, int* __restrict__ b, int n) {
    int i = blockIdx.x * blockDim.x + threadIdx.x;
    if (i < n) { a[i] = 0; b[i] = 0; }
}
__global__ void hist_kernel(const int* __restrict__ ei, int* __restrict__ hist, int E) {
    int i = blockIdx.x * blockDim.x + threadIdx.x;
    if (i < E) atomicAdd(hist + ei[E + i], 1);
}
__global__ void scan_kernel(const int* __restrict__ hist, int* __restrict__ rowstart, int n) {
    __shared__ int wsum[32];
    __shared__ int s_carry;
    int t = threadIdx.x;
    int lane = t & 31, w = t >> 5;
    if (t == 0) s_carry = 0;
    __syncthreads();
    for (int base = 0; base < n; base += 1024) {
        int idx = base + t;
        int v = (idx < n) ? hist[idx] : 0;
        int x = v;
        #pragma unroll
        for (int o = 1; o < 32; o <<= 1) {
            int y = __shfl_up_sync(0xffffffffu, x, o);
            if (lane >= o) x += y;
        }
        if (lane == 31) wsum[w] = x;
        __syncthreads();
        if (w == 0) {
            int s = wsum[lane];
            #pragma unroll
            for (int o = 1; o < 32; o <<= 1) {
                int y = __shfl_up_sync(0xffffffffu, s, o);
                if (lane >= o) s += y;
            }
            wsum[lane] = s;
        }
        __syncthreads();
        int incl = x + (w > 0 ? wsum[w - 1] : 0);
        int carry = s_carry;
        if (idx < n) rowstart[idx] = carry + incl - v;
        __syncthreads();
        if (t == 0) s_carry = carry + wsum[31];
        __syncthreads();
    }
    if (t == 0) rowstart[n] = s_carry;
}
__global__ void scatter_kernel(const int* __restrict__ ei, const int* __restrict__ ea,
                               const int* __restrict__ rowstart, int* __restrict__ cnt,
                               int* __restrict__ srcs, int* __restrict__ codes, int E) {
    int i = blockIdx.x * blockDim.x + threadIdx.x;
    if (i < E) {
        int dst = ei[E + i];
        int pos = rowstart[dst] + atomicAdd(cnt + dst, 1);
        srcs[pos]  = ei[i];
        codes[pos] = ea[i * 3] * 64 + ea[i * 3 + 1] * 8 + ea[i * 3 + 2];
    }
}

// ---------------- embedding sum + LayerNorm (atom path, fp16 table, fp16 out) ----------------
__global__ void embed_ln_kernel(const int* __restrict__ ids,
                                const __half* __restrict__ emb,
                                const float* __restrict__ g,
                                const float* __restrict__ bta,
                                __half* __restrict__ out,
                                int F, int V) {
    int n = blockIdx.x;
    int t = threadIdx.x;
    __shared__ int   sid[16];
    __shared__ float shm[16];
    if (t < F) sid[t] = ids[(size_t)n * F + t];
    __syncthreads();

    float x[3];
    #pragma unroll
    for (int j = 0; j < 3; j++) {
        int d = t + j * 256;
        float s = 0.f;
        for (int f = 0; f < F; f++)
            s += __half2float(emb[((size_t)(f * V + sid[f])) * D + d]);
        x[j] = s;
    }
    float s1 = x[0] + x[1] + x[2];
    float s2 = x[0]*x[0] + x[1]*x[1] + x[2]*x[2];
    block_reduce2(s1, s2, shm);
    float mean = s1 * (1.0f / D);
    float var  = s2 * (1.0f / D) - mean * mean;
    float inv  = rsqrtf(var + 1e-5f);
    __half* o = out + (size_t)n * D;
    #pragma unroll
    for (int j = 0; j < 3; j++) {
        int d = t + j * 256;
        o[d] = __float2half_rn((x[j] - mean) * inv * g[d] + bta[d]);
    }
}

// ---------------- bond table embed+LN: one block per code (fp32 table, tiny) ----------------
__global__ void embed_ln_bond_kernel(const float* __restrict__ emb,
                                     const float* __restrict__ g,
                                     const float* __restrict__ bta,
                                     __half* __restrict__ out) {
    int n = blockIdx.x;
    int t = threadIdx.x;
    __shared__ float shm[16];
    int id0 = (n >> 6) & 7, id1 = (n >> 3) & 7, id2 = n & 7;

    float x[3];
    #pragma unroll
    for (int j = 0; j < 3; j++) {
        int d = t + j * 256;
        x[j] = emb[((size_t)(0 * 8 + id0)) * D + d]
             + emb[((size_t)(1 * 8 + id1)) * D + d]
             + emb[((size_t)(2 * 8 + id2)) * D + d];
    }
    float s1 = x[0] + x[1] + x[2];
    float s2 = x[0]*x[0] + x[1]*x[1] + x[2]*x[2];
    block_reduce2(s1, s2, shm);
    float mean = s1 * (1.0f / D);
    float var  = s2 * (1.0f / D) - mean * mean;
    float inv  = rsqrtf(var + 1e-5f);
    __half* o = out + (size_t)n * D;
    #pragma unroll
    for (int j = 0; j < 3; j++) {
        int d = t + j * 256;
        o[d] = __float2half_rn((x[j] - mean) * inv * g[d] + bta[d]);
    }
}

// ---------------- CSR edge aggregation: a16[n] = fp16(h16[n] + sum relu(h16[src]+etab[code])) ----------------
__global__ void edge_agg_kernel(const int* __restrict__ rowstart,
                                const int* __restrict__ srcs,
                                const int* __restrict__ codes,
                                const __half* __restrict__ h16,
                                const __half* __restrict__ etab,
                                __half* __restrict__ a16) {
    int n = blockIdx.x;
    int t = threadIdx.x;  // 192 threads * 4 floats = 768
    const __half2* zp = (const __half2*)(h16 + (size_t)n * D) + t * 2;
    float2 z0 = __half22float2(zp[0]);
    float2 z1 = __half22float2(zp[1]);
    float4 z = make_float4(z0.x, z0.y, z1.x, z1.y);
    int beg = __ldg(rowstart + n);
    int end = __ldg(rowstart + n + 1);
    for (int p = beg; p < end; p++) {
        int src = __ldg(srcs + p);
        int c   = __ldg(codes + p);
        const __half2* hp = (const __half2*)(h16 + (size_t)src * D) + t * 2;
        const __half2* ep = (const __half2*)(etab + (size_t)c * D) + t * 2;
        float2 h0 = __half22float2(hp[0]);
        float2 h1 = __half22float2(hp[1]);
        float2 e0 = __half22float2(ep[0]);
        float2 e1 = __half22float2(ep[1]);
        z.x += fmaxf(h0.x + e0.x, 0.f);
        z.y += fmaxf(h0.y + e0.y, 0.f);
        z.z += fmaxf(h1.x + e1.x, 0.f);
        z.w += fmaxf(h1.y + e1.y, 0.f);
    }
    __half2* o = (__half2*)(a16 + (size_t)n * D) + t * 2;
    o[0] = __floats2half2_rn(z.x, z.y);
    o[1] = __floats2half2_rn(z.z, z.w);
}

// ---------------- fused gelu + residual + LayerNorm (+ h16 mirror) ----------------
__global__ void ln_res_kernel(const float* __restrict__ z,
                              const float* __restrict__ hin,
                              const float* __restrict__ g,
                              const float* __restrict__ bta,
                              float* __restrict__ out,
                              __half* __restrict__ h16) {
    int n = blockIdx.x;
    int t = threadIdx.x;
    __shared__ float shm[16];
    float x[3];
    #pragma unroll
    for (int j = 0; j < 3; j++) {
        int d = t + j * 256;
        x[j] = gelu_f(z[(size_t)n * D + d]) + hin[(size_t)n * D + d];
    }
    float s1 = x[0] + x[1] + x[2];
    float s2 = x[0]*x[0] + x[1]*x[1] + x[2]*x[2];
    block_reduce2(s1, s2, shm);
    float mean = s1 * (1.0f / D);
    float var  = s2 * (1.0f / D) - mean * mean;
    float inv  = rsqrtf(var + 1e-5f);
    #pragma unroll
    for (int j = 0; j < 3; j++) {
        int d = t + j * 256;
        float r = (x[j] - mean) * inv * g[d] + bta[d];
        out[(size_t)n * D + d] = r;
        if (h16) h16[(size_t)n * D + d] = __float2half_rn(r);
    }
}

// ---------------- host orchestration ----------------
extern "C" void kernel_launch(void* const* d_in, const int* in_sizes, int n_in,
                              void* d_out, int out_size) {
    const int*   x          = (const int*)d_in[0];
    const int*   edge_attr  = (const int*)d_in[1];
    const int*   edge_index = (const int*)d_in[2];
    const float* atom_emb   = (const float*)d_in[3];
    const float* atom_ln_g  = (const float*)d_in[4];
    const float* atom_ln_b  = (const float*)d_in[5];
    const float* atom_w1    = (const float*)d_in[6];
    const float* atom_b1    = (const float*)d_in[7];
    const float* atom_w2    = (const float*)d_in[8];
    const float* atom_b2    = (const float*)d_in[9];
    const float* bond_emb   = (const float*)d_in[10];
    const float* bond_ln_g  = (const float*)d_in[11];
    const float* bond_ln_b  = (const float*)d_in[12];
    const float* bond_w1    = (const float*)d_in[13];
    const float* bond_b1    = (const float*)d_in[14];
    const float* bond_w2    = (const float*)d_in[15];
    const float* bond_b2    = (const float*)d_in[16];
    const float* conv_w1    = (const float*)d_in[17];
    const float* conv_b1    = (const float*)d_in[18];
    const float* conv_w2    = (const float*)d_in[19];
    const float* conv_b2    = (const float*)d_in[20];
    const float* ln_g       = (const float*)d_in[21];
    const float* ln_b       = (const float*)d_in[22];
    float* out = (float*)d_out;

    int N = in_sizes[0] / 9;
    int E = in_sizes[1] / 3;
    if (N > MAXN) N = MAXN;
    if (E > MAXE) E = MAXE;

    float *phA, *phB, *pz;
    int *phist, *pcnt, *prow, *psrcs, *pcodes;
    __half *petab, *pbtmp, *ph16, *pa16, *pt16, *pw16, *paemb;
    cudaGetSymbolAddress((void**)&phA,    g_hA);
    cudaGetSymbolAddress((void**)&phB,    g_hB);
    cudaGetSymbolAddress((void**)&pz,     g_z);
    cudaGetSymbolAddress((void**)&phist,  g_hist);
    cudaGetSymbolAddress((void**)&pcnt,   g_cnt);
    cudaGetSymbolAddress((void**)&prow,   g_rowstart);
    cudaGetSymbolAddress((void**)&psrcs,  g_srcs);
    cudaGetSymbolAddress((void**)&pcodes, g_codes);
    cudaGetSymbolAddress((void**)&petab,  g_etab);
    cudaGetSymbolAddress((void**)&pbtmp,  g_btmp);
    cudaGetSymbolAddress((void**)&ph16,   g_h16);
    cudaGetSymbolAddress((void**)&pa16,   g_a16);
    cudaGetSymbolAddress((void**)&pt16,   g_t16);
    cudaGetSymbolAddress((void**)&pw16,   g_w16);
    cudaGetSymbolAddress((void**)&paemb,  g_aemb16);

    cudaFuncSetAttribute(gemm_kernel<0, false>, cudaFuncAttributeMaxDynamicSharedMemorySize, GEMM_SMEM);
    cudaFuncSetAttribute(gemm_kernel<0, true>,  cudaFuncAttributeMaxDynamicSharedMemorySize, GEMM_SMEM);
    cudaFuncSetAttribute(gemm_kernel<1, true>,  cudaFuncAttributeMaxDynamicSharedMemorySize, GEMM_SMEM);
    cudaFuncSetAttribute(gemm_kernel<2, true>,  cudaFuncAttributeMaxDynamicSharedMemorySize, GEMM_SMEM);

    WPtrs wp;
    wp.p[0] = atom_w1; wp.p[1] = atom_w2; wp.p[2] = bond_w1;
    wp.p[3] = bond_w2; wp.p[4] = conv_w1; wp.p[5] = conv_w2;

    auto WT = [&](int i) { return pw16 + (size_t)i * D * D; };
    dim3 gN(D / BN, (N + BM - 1) / BM);
    dim3 gB(D / BN, (NBOND + BM - 1) / BM);

    int emb4 = 9 * 128 * D / 4;

    // launches 0-4
    transpose_all_kernel<<<dim3(D / 32, D / 32, 12), dim3(32, 8)>>>(wp, pw16);        // 0
    zero2_kernel<<<(N + 255) / 256, 256>>>(phist, pcnt, N);                            // 1
    cvt_emb_kernel<<<(emb4 + 255) / 256, 256>>>((const float4*)atom_emb, (__half2*)paemb, emb4); // 2
    embed_ln_kernel<<<N, 256>>>(x, paemb, atom_ln_g, atom_ln_b, pa16, 9, 128);         // 3
    embed_ln_bond_kernel<<<NBOND, 256>>>(bond_emb, bond_ln_g, bond_ln_b, pbtmp);       // 4
    // launch 5: full N-GEMM -> ncu
    gemm_kernel<2, true ><<<gN, GEMM_THREADS, GEMM_SMEM>>>(pa16, WT(0), atom_b1, pt16, N, nullptr);   // 5
    // atom GEMM2 writes fp32 h AND fp16 mirror (seed fused)
    gemm_kernel<0, false><<<gN, GEMM_THREADS, GEMM_SMEM>>>(pt16, WT(1), atom_b2, phA, N, ph16);

    // CSR build
    hist_kernel<<<(E + 255) / 256, 256>>>(edge_index, phist, E);
    scan_kernel<<<1, 1024>>>(phist, prow, N);
    scatter_kernel<<<(E + 255) / 256, 256>>>(edge_index, edge_attr, prow, pcnt, psrcs, pcodes, E);

    // bond-table encoder GEMMs (512 rows)
    gemm_kernel<2, true ><<<gB, GEMM_THREADS, GEMM_SMEM>>>(pbtmp, WT(2), bond_b1, pbtmp + (size_t)NBOND * D, NBOND, nullptr);
    gemm_kernel<0, true ><<<gB, GEMM_THREADS, GEMM_SMEM>>>(pbtmp + (size_t)NBOND * D, WT(3), bond_b2, petab, NBOND, nullptr);

    const float* hcur = phA;
    float* hnext = phB;
    for (int l = 0; l < N_LAYERS; l++) {
        // a16[n] = fp16( h16[n] + sum_{edges->n} relu(h16[src] + etab[code]) )
        edge_agg_kernel<<<N, 192>>>(prow, psrcs, pcodes, ph16, petab, pa16);
        // conv MLP
        gemm_kernel<1, true ><<<gN, GEMM_THREADS, GEMM_SMEM>>>(pa16, WT(4 + l), conv_b1 + l * D, pt16, N, nullptr);
        gemm_kernel<0, false><<<gN, GEMM_THREADS, GEMM_SMEM>>>(pt16, WT(8 + l), conv_b2 + l * D, pz, N, nullptr);
        // h = LN(gelu(z) + h_in); refresh h16 mirror (except last layer)
        float*  dst = (l == N_LAYERS - 1) ? out : hnext;
        __half* mir = (l == N_LAYERS - 1) ? nullptr : ph16;
        ln_res_kernel<<<N, 256>>>(pz, hcur, ln_g + l * D, ln_b + l * D, dst, mir);

        float* old = (float*)hcur;
        hcur = dst;
        hnext = old;
    }
}

// round 17
// speedup vs baseline: 1.8765x; 1.0382x over previous
#include <cuda_runtime.h>
#include <cuda_fp16.h>
#include <cstdint>
#include <cstddef>

#define D 768
#define N_LAYERS 4
#define MAXN 50000
#define MAXE 100000
#define NBOND 512   // 8^3 distinct edge-attr triples

// ---------------- static scratch (allocation-free rule) ----------------
__device__ float  g_hA [(size_t)MAXN * D];
__device__ float  g_hB [(size_t)MAXN * D];
__device__ float  g_z  [(size_t)MAXN * D];                  // conv-MLP output (fp32)
__device__ int    g_hist[(size_t)MAXN];
__device__ int    g_cnt [(size_t)MAXN];
__device__ int    g_rowstart[(size_t)MAXN + 1];
__device__ int    g_srcs [(size_t)MAXE];
__device__ int    g_codes[(size_t)MAXE];
__device__ __align__(128) __half g_etab[(size_t)NBOND * D]; // bond-type table (fp16)
__device__ __align__(128) __half g_btmp[(size_t)2 * NBOND * D];
__device__ __align__(128) __half g_h16[(size_t)MAXN * D];   // fp16 mirror of h
__device__ __align__(128) __half g_a16[(size_t)MAXN * D];   // GEMM-1 inputs (fp16)
__device__ __align__(128) __half g_t16[(size_t)MAXN * D];   // hidden activations (fp16)
__device__ __align__(128) __half g_w16[(size_t)12 * D * D]; // transposed fp16 weights [n][k]
__device__ __align__(128) __half g_aemb16[(size_t)9 * 128 * D]; // fp16 atom embedding table

// ---------------- tiny helpers ----------------
__device__ __forceinline__ float gelu_f(float x) {
    const float k0 = 0.7978845608028654f;
    const float k1 = 0.044715f;
    return 0.5f * x * (1.0f + tanhf(k0 * (x + k1 * x * x * x)));
}
template <int ACT>
__device__ __forceinline__ float actf(float x) {
    if (ACT == 1) return fmaxf(x, 0.0f);
    if (ACT == 2) return gelu_f(x);
    return x;
}
// NW = number of warps in the block
template <int NW>
__device__ __forceinline__ void block_reduce2w(float& s1, float& s2, float* shm) {
    #pragma unroll
    for (int o = 16; o > 0; o >>= 1) {
        s1 += __shfl_xor_sync(0xffffffffu, s1, o);
        s2 += __shfl_xor_sync(0xffffffffu, s2, o);
    }
    int wid = threadIdx.x >> 5, lane = threadIdx.x & 31;
    if (lane == 0) { shm[wid] = s1; shm[8 + wid] = s2; }
    __syncthreads();
    float a = 0.f, b = 0.f;
    #pragma unroll
    for (int i = 0; i < NW; i++) { a += shm[i]; b += shm[8 + i]; }
    s1 = a; s2 = b;
}

__device__ __forceinline__ void cp_async16(void* s, const void* g) {
    uint32_t sa = (uint32_t)__cvta_generic_to_shared(s);
    asm volatile("cp.async.cg.shared.global [%0], [%1], 16;" :: "r"(sa), "l"(g));
}
__device__ __forceinline__ void ldsm_x4(uint32_t* r, uint32_t addr) {
    asm volatile("ldmatrix.sync.aligned.m8n8.x4.shared.b16 {%0,%1,%2,%3}, [%4];"
                 : "=r"(r[0]), "=r"(r[1]), "=r"(r[2]), "=r"(r[3]) : "r"(addr));
}
__device__ __forceinline__ void mma_f16(float* c, const uint32_t* a, uint32_t b0, uint32_t b1) {
    asm volatile(
        "mma.sync.aligned.m16n8k16.row.col.f32.f16.f16.f32 "
        "{%0,%1,%2,%3},{%4,%5,%6,%7},{%8,%9},{%0,%1,%2,%3};"
        : "+f"(c[0]), "+f"(c[1]), "+f"(c[2]), "+f"(c[3])
        : "r"(a[0]), "r"(a[1]), "r"(a[2]), "r"(a[3]), "r"(b0), "r"(b1));
}

// ---------------- fp16 tensor-core GEMM (2 CTAs/SM, BK=64, 3-stage) ----------------
#define BM 128
#define BN 128
#define BK 64
#define NT (D / BK)                      // 12 iterations
#define NSTAGE 3
#define SROW 144                         // 64 halves (128B) + 16B pad -> LDSM conflict-free
#define A_BYTES (BM * SROW)              // 18432
#define STAGE_BYTES (A_BYTES + BN * SROW)  // 36864
#define GEMM_THREADS 256
#define GEMM_SMEM (NSTAGE * STAGE_BYTES)   // 110592 (2 CTAs = 221184 <= 228KB)

// HOUT: fp16 C output. mirror (optional, HOUT=false only): also write fp16 copy of C.
template <int ACT, bool HOUT>
__global__ void __launch_bounds__(GEMM_THREADS, 2)
gemm_kernel(const __half* __restrict__ A, const __half* __restrict__ Wt,
            const float* __restrict__ bias, void* __restrict__ Cv, int M,
            __half* __restrict__ mirror)
{
    extern __shared__ char smem[];
    const int t  = threadIdx.x;
    const int m0 = blockIdx.y * BM;
    const int n0 = blockIdx.x * BN;
    const uint32_t sbu = (uint32_t)__cvta_generic_to_shared(smem);

    auto load_stage = [&](int s, int kt) {
        char* abuf = smem + s * STAGE_BYTES;
        char* bbuf = abuf + A_BYTES;
        #pragma unroll
        for (int i = 0; i < 4; i++) {   // A: 128 rows x 128B
            int q = t + i * GEMM_THREADS;
            int row = q >> 3, c = q & 7;
            int m = m0 + row; m = (m < M) ? m : (M - 1);
            cp_async16(abuf + row * SROW + c * 16, A + (size_t)m * D + kt * BK + c * 8);
        }
        #pragma unroll
        for (int i = 0; i < 4; i++) {   // B: 128 rows x 128B
            int q = t + i * GEMM_THREADS;
            int row = q >> 3, c = q & 7;
            cp_async16(bbuf + row * SROW + c * 16, Wt + (size_t)(n0 + row) * D + kt * BK + c * 8);
        }
    };

    float acc[2][8][4];
    #pragma unroll
    for (int i = 0; i < 2; i++)
        #pragma unroll
        for (int j = 0; j < 8; j++)
            #pragma unroll
            for (int k = 0; k < 4; k++) acc[i][j][k] = 0.f;

    #pragma unroll
    for (int s = 0; s < NSTAGE; s++) {
        load_stage(s, s);
        asm volatile("cp.async.commit_group;" ::: "memory");
    }

    const int lane = t & 31, wid = t >> 5;
    const int wm = (wid & 3) * 32;
    const int wn = (wid >> 2) * 64;
    const int gr = lane >> 2, tig = lane & 3;

    const uint32_t a_off0 = (uint32_t)((wm + (lane & 15)) * SROW + (lane >> 4) * 16);
    const uint32_t b_off0 = (uint32_t)((wn + (lane & 7) + ((lane >> 4) & 1) * 8) * SROW
                                       + ((lane >> 3) & 1) * 16);

    for (int kt = 0; kt < NT; ++kt) {
        const int s = kt % NSTAGE;
        asm volatile("cp.async.wait_group %0;" :: "n"(NSTAGE - 1) : "memory");
        __syncthreads();
        const uint32_t sa = sbu + s * STAGE_BYTES;
        const uint32_t sb = sa + A_BYTES;
        #pragma unroll
        for (int kc = 0; kc < 4; kc++) {
            uint32_t af[2][4];
            #pragma unroll
            for (int mi = 0; mi < 2; mi++)
                ldsm_x4(af[mi], sa + a_off0 + mi * 16 * SROW + kc * 32);
            #pragma unroll
            for (int jp = 0; jp < 4; jp++) {
                uint32_t bf[4];
                ldsm_x4(bf, sb + b_off0 + jp * 16 * SROW + kc * 32);
                mma_f16(acc[0][jp * 2 + 0], af[0], bf[0], bf[1]);
                mma_f16(acc[1][jp * 2 + 0], af[1], bf[0], bf[1]);
                mma_f16(acc[0][jp * 2 + 1], af[0], bf[2], bf[3]);
                mma_f16(acc[1][jp * 2 + 1], af[1], bf[2], bf[3]);
            }
        }
        __syncthreads();
        if (kt + NSTAGE < NT) load_stage(s, kt + NSTAGE);
        asm volatile("cp.async.commit_group;" ::: "memory");
    }

    #pragma unroll
    for (int mi = 0; mi < 2; mi++) {
        int row0 = m0 + wm + mi * 16 + gr;
        #pragma unroll
        for (int ni = 0; ni < 8; ni++) {
            int col = n0 + wn + ni * 8 + tig * 2;
            float bv0 = __ldg(bias + col), bv1 = __ldg(bias + col + 1);
            float v0 = actf<ACT>(acc[mi][ni][0] + bv0);
            float v1 = actf<ACT>(acc[mi][ni][1] + bv1);
            float v2 = actf<ACT>(acc[mi][ni][2] + bv0);
            float v3 = actf<ACT>(acc[mi][ni][3] + bv1);
            if (HOUT) {
                __half* C = (__half*)Cv;
                if (row0 < M)
                    *(__half2*)(C + (size_t)row0 * D + col) = __floats2half2_rn(v0, v1);
                if (row0 + 8 < M)
                    *(__half2*)(C + (size_t)(row0 + 8) * D + col) = __floats2half2_rn(v2, v3);
            } else {
                float* C = (float*)Cv;
                if (row0 < M) {
                    *(float2*)(C + (size_t)row0 * D + col) = make_float2(v0, v1);
                    if (mirror)
                        *(__half2*)(mirror + (size_t)row0 * D + col) = __floats2half2_rn(v0, v1);
                }
                if (row0 + 8 < M) {
                    *(float2*)(C + (size_t)(row0 + 8) * D + col) = make_float2(v2, v3);
                    if (mirror)
                        *(__half2*)(mirror + (size_t)(row0 + 8) * D + col) = __floats2half2_rn(v2, v3);
                }
            }
        }
    }
}

// ---------------- weight transpose + fp16 convert (one launch) ----------------
struct WPtrs { const float* p[6]; };
__global__ void transpose_all_kernel(WPtrs w, __half* __restrict__ wt) {
    int mat = blockIdx.z;
    const float* W = (mat < 4) ? w.p[mat]
                   : (mat < 8) ? w.p[4] + (size_t)(mat - 4) * D * D
                               : w.p[5] + (size_t)(mat - 8) * D * D;
    __half* Wt = wt + (size_t)mat * D * D;
    __shared__ float tile[32][33];
    int bx = blockIdx.x * 32;
    int by = blockIdx.y * 32;
    int tx = threadIdx.x, ty = threadIdx.y;
    #pragma unroll
    for (int j = 0; j < 32; j += 8)
        tile[ty + j][tx] = W[(size_t)(by + ty + j) * D + bx + tx];
    __syncthreads();
    #pragma unroll
    for (int j = 0; j < 32; j += 8)
        Wt[(size_t)(bx + ty + j) * D + by + tx] = __float2half_rn(tile[tx][ty + j]);
}

// ---------------- atom embedding table -> fp16 ----------------
__global__ void cvt_emb_kernel(const float4* __restrict__ src, __half2* __restrict__ dst, int n4) {
    int i = blockIdx.x * blockDim.x + threadIdx.x;
    if (i < n4) {
        float4 v = src[i];
        dst[i * 2 + 0] = __floats2half2_rn(v.x, v.y);
        dst[i * 2 + 1] = __floats2half2_rn(v.z, v.w);
    }
}

// ---------------- CSR build ----------------
__global__ void zero2_kernel(int* __restrict__ a, int* __restrict__ b, int n) {
    int i = blockIdx.x * blockDim.x + threadIdx.x;
    if (i < n) { a[i] = 0; b[i] = 0; }
}
__global__ void hist_kernel(const int* __restrict__ ei, int* __restrict__ hist, int E) {
    int i = blockIdx.x * blockDim.x + threadIdx.x;
    if (i < E) atomicAdd(hist + ei[E + i], 1);
}
__global__ void scan_kernel(const int* __restrict__ hist, int* __restrict__ rowstart, int n) {
    __shared__ int wsum[32];
    __shared__ int s_carry;
    int t = threadIdx.x;
    int lane = t & 31, w = t >> 5;
    if (t == 0) s_carry = 0;
    __syncthreads();
    for (int base = 0; base < n; base += 1024) {
        int idx = base + t;
        int v = (idx < n) ? hist[idx] : 0;
        int x = v;
        #pragma unroll
        for (int o = 1; o < 32; o <<= 1) {
            int y = __shfl_up_sync(0xffffffffu, x, o);
            if (lane >= o) x += y;
        }
        if (lane == 31) wsum[w] = x;
        __syncthreads();
        if (w == 0) {
            int s = wsum[lane];
            #pragma unroll
            for (int o = 1; o < 32; o <<= 1) {
                int y = __shfl_up_sync(0xffffffffu, s, o);
                if (lane >= o) s += y;
            }
            wsum[lane] = s;
        }
        __syncthreads();
        int incl = x + (w > 0 ? wsum[w - 1] : 0);
        int carry = s_carry;
        if (idx < n) rowstart[idx] = carry + incl - v;
        __syncthreads();
        if (t == 0) s_carry = carry + wsum[31];
        __syncthreads();
    }
    if (t == 0) rowstart[n] = s_carry;
}
__global__ void scatter_kernel(const int* __restrict__ ei, const int* __restrict__ ea,
                               const int* __restrict__ rowstart, int* __restrict__ cnt,
                               int* __restrict__ srcs, int* __restrict__ codes, int E) {
    int i = blockIdx.x * blockDim.x + threadIdx.x;
    if (i < E) {
        int dst = ei[E + i];
        int pos = rowstart[dst] + atomicAdd(cnt + dst, 1);
        srcs[pos]  = ei[i];
        codes[pos] = ea[i * 3] * 64 + ea[i * 3 + 1] * 8 + ea[i * 3 + 2];
    }
}

// ---------------- atom embedding sum + LayerNorm (vectorized, 192 thr) ----------------
// Each thread owns 4 contiguous halves: 9 x LDG.64 + fp32 accumulate.
__global__ void embed_ln_atom_kernel(const int* __restrict__ ids,
                                     const __half* __restrict__ emb,
                                     const float* __restrict__ g,
                                     const float* __restrict__ bta,
                                     __half* __restrict__ out) {
    int n = blockIdx.x;
    int t = threadIdx.x;              // 192
    __shared__ int   sid[9];
    __shared__ float shm[16];
    if (t < 9) sid[t] = ids[(size_t)n * 9 + t];
    __syncthreads();

    int d0 = t * 4;
    float4 acc = make_float4(0.f, 0.f, 0.f, 0.f);
    #pragma unroll
    for (int f = 0; f < 9; f++) {
        const uint2 v = *(const uint2*)(emb + ((size_t)(f * 128 + sid[f])) * D + d0);
        float2 fa = __half22float2(*(const __half2*)&v.x);
        float2 fb = __half22float2(*(const __half2*)&v.y);
        acc.x += fa.x; acc.y += fa.y; acc.z += fb.x; acc.w += fb.y;
    }
    float s1 = acc.x + acc.y + acc.z + acc.w;
    float s2 = acc.x*acc.x + acc.y*acc.y + acc.z*acc.z + acc.w*acc.w;
    block_reduce2w<6>(s1, s2, shm);
    float mean = s1 * (1.0f / D);
    float var  = s2 * (1.0f / D) - mean * mean;
    float inv  = rsqrtf(var + 1e-5f);

    float4 gv = *(const float4*)(g + d0);
    float4 bv = *(const float4*)(bta + d0);
    __half2* o = (__half2*)(out + (size_t)n * D) + t * 2;
    o[0] = __floats2half2_rn((acc.x - mean) * inv * gv.x + bv.x,
                             (acc.y - mean) * inv * gv.y + bv.y);
    o[1] = __floats2half2_rn((acc.z - mean) * inv * gv.z + bv.z,
                             (acc.w - mean) * inv * gv.w + bv.w);
}

// ---------------- bond table embed+LN: one block per code (fp32 table, tiny) ----------------
__global__ void embed_ln_bond_kernel(const float* __restrict__ emb,
                                     const float* __restrict__ g,
                                     const float* __restrict__ bta,
                                     __half* __restrict__ out) {
    int n = blockIdx.x;
    int t = threadIdx.x;
    __shared__ float shm[16];
    int id0 = (n >> 6) & 7, id1 = (n >> 3) & 7, id2 = n & 7;

    float x[3];
    #pragma unroll
    for (int j = 0; j < 3; j++) {
        int d = t + j * 256;
        x[j] = emb[((size_t)(0 * 8 + id0)) * D + d]
             + emb[((size_t)(1 * 8 + id1)) * D + d]
             + emb[((size_t)(2 * 8 + id2)) * D + d];
    }
    float s1 = x[0] + x[1] + x[2];
    float s2 = x[0]*x[0] + x[1]*x[1] + x[2]*x[2];
    block_reduce2w<8>(s1, s2, shm);
    float mean = s1 * (1.0f / D);
    float var  = s2 * (1.0f / D) - mean * mean;
    float inv  = rsqrtf(var + 1e-5f);
    __half* o = out + (size_t)n * D;
    #pragma unroll
    for (int j = 0; j < 3; j++) {
        int d = t + j * 256;
        o[d] = __float2half_rn((x[j] - mean) * inv * g[d] + bta[d]);
    }
}

// ---------------- CSR edge aggregation: a16[n] = fp16(h16[n] + sum relu(h16[src]+etab[code])) ----------------
__global__ void edge_agg_kernel(const int* __restrict__ rowstart,
                                const int* __restrict__ srcs,
                                const int* __restrict__ codes,
                                const __half* __restrict__ h16,
                                const __half* __restrict__ etab,
                                __half* __restrict__ a16) {
    int n = blockIdx.x;
    int t = threadIdx.x;  // 192 threads * 4 floats = 768
    const __half2* zp = (const __half2*)(h16 + (size_t)n * D) + t * 2;
    float2 z0 = __half22float2(zp[0]);
    float2 z1 = __half22float2(zp[1]);
    float4 z = make_float4(z0.x, z0.y, z1.x, z1.y);
    int beg = __ldg(rowstart + n);
    int end = __ldg(rowstart + n + 1);
    for (int p = beg; p < end; p++) {
        int src = __ldg(srcs + p);
        int c   = __ldg(codes + p);
        const __half2* hp = (const __half2*)(h16 + (size_t)src * D) + t * 2;
        const __half2* ep = (const __half2*)(etab + (size_t)c * D) + t * 2;
        float2 h0 = __half22float2(hp[0]);
        float2 h1 = __half22float2(hp[1]);
        float2 e0 = __half22float2(ep[0]);
        float2 e1 = __half22float2(ep[1]);
        z.x += fmaxf(h0.x + e0.x, 0.f);
        z.y += fmaxf(h0.y + e0.y, 0.f);
        z.z += fmaxf(h1.x + e1.x, 0.f);
        z.w += fmaxf(h1.y + e1.y, 0.f);
    }
    __half2* o = (__half2*)(a16 + (size_t)n * D) + t * 2;
    o[0] = __floats2half2_rn(z.x, z.y);
    o[1] = __floats2half2_rn(z.z, z.w);
}

// ---------------- fused gelu + residual + LayerNorm (+ h16 mirror) ----------------
__global__ void ln_res_kernel(const float* __restrict__ z,
                              const float* __restrict__ hin,
                              const float* __restrict__ g,
                              const float* __restrict__ bta,
                              float* __restrict__ out,
                              __half* __restrict__ h16) {
    int n = blockIdx.x;
    int t = threadIdx.x;
    __shared__ float shm[16];
    float x[3];
    #pragma unroll
    for (int j = 0; j < 3; j++) {
        int d = t + j * 256;
        x[j] = gelu_f(z[(size_t)n * D + d]) + hin[(size_t)n * D + d];
    }
    float s1 = x[0] + x[1] + x[2];
    float s2 = x[0]*x[0] + x[1]*x[1] + x[2]*x[2];
    block_reduce2w<8>(s1, s2, shm);
    float mean = s1 * (1.0f / D);
    float var  = s2 * (1.0f / D) - mean * mean;
    float inv  = rsqrtf(var + 1e-5f);
    #pragma unroll
    for (int j = 0; j < 3; j++) {
        int d = t + j * 256;
        float r = (x[j] - mean) * inv * g[d] + bta[d];
        out[(size_t)n * D + d] = r;
        if (h16) h16[(size_t)n * D + d] = __float2half_rn(r);
    }
}

// ---------------- host orchestration ----------------
extern "C" void kernel_launch(void* const* d_in, const int* in_sizes, int n_in,
                              void* d_out, int out_size) {
    const int*   x          = (const int*)d_in[0];
    const int*   edge_attr  = (const int*)d_in[1];
    const int*   edge_index = (const int*)d_in[2];
    const float* atom_emb   = (const float*)d_in[3];
    const float* atom_ln_g  = (const float*)d_in[4];
    const float* atom_ln_b  = (const float*)d_in[5];
    const float* atom_w1    = (const float*)d_in[6];
    const float* atom_b1    = (const float*)d_in[7];
    const float* atom_w2    = (const float*)d_in[8];
    const float* atom_b2    = (const float*)d_in[9];
    const float* bond_emb   = (const float*)d_in[10];
    const float* bond_ln_g  = (const float*)d_in[11];
    const float* bond_ln_b  = (const float*)d_in[12];
    const float* bond_w1    = (const float*)d_in[13];
    const float* bond_b1    = (const float*)d_in[14];
    const float* bond_w2    = (const float*)d_in[15];
    const float* bond_b2    = (const float*)d_in[16];
    const float* conv_w1    = (const float*)d_in[17];
    const float* conv_b1    = (const float*)d_in[18];
    const float* conv_w2    = (const float*)d_in[19];
    const float* conv_b2    = (const float*)d_in[20];
    const float* ln_g       = (const float*)d_in[21];
    const float* ln_b       = (const float*)d_in[22];
    float* out = (float*)d_out;

    int N = in_sizes[0] / 9;
    int E = in_sizes[1] / 3;
    if (N > MAXN) N = MAXN;
    if (E > MAXE) E = MAXE;

    float *phA, *phB, *pz;
    int *phist, *pcnt, *prow, *psrcs, *pcodes;
    __half *petab, *pbtmp, *ph16, *pa16, *pt16, *pw16, *paemb;
    cudaGetSymbolAddress((void**)&phA,    g_hA);
    cudaGetSymbolAddress((void**)&phB,    g_hB);
    cudaGetSymbolAddress((void**)&pz,     g_z);
    cudaGetSymbolAddress((void**)&phist,  g_hist);
    cudaGetSymbolAddress((void**)&pcnt,   g_cnt);
    cudaGetSymbolAddress((void**)&prow,   g_rowstart);
    cudaGetSymbolAddress((void**)&psrcs,  g_srcs);
    cudaGetSymbolAddress((void**)&pcodes, g_codes);
    cudaGetSymbolAddress((void**)&petab,  g_etab);
    cudaGetSymbolAddress((void**)&pbtmp,  g_btmp);
    cudaGetSymbolAddress((void**)&ph16,   g_h16);
    cudaGetSymbolAddress((void**)&pa16,   g_a16);
    cudaGetSymbolAddress((void**)&pt16,   g_t16);
    cudaGetSymbolAddress((void**)&pw16,   g_w16);
    cudaGetSymbolAddress((void**)&paemb,  g_aemb16);

    cudaFuncSetAttribute(gemm_kernel<0, false>, cudaFuncAttributeMaxDynamicSharedMemorySize, GEMM_SMEM);
    cudaFuncSetAttribute(gemm_kernel<0, true>,  cudaFuncAttributeMaxDynamicSharedMemorySize, GEMM_SMEM);
    cudaFuncSetAttribute(gemm_kernel<1, true>,  cudaFuncAttributeMaxDynamicSharedMemorySize, GEMM_SMEM);
    cudaFuncSetAttribute(gemm_kernel<2, true>,  cudaFuncAttributeMaxDynamicSharedMemorySize, GEMM_SMEM);

    WPtrs wp;
    wp.p[0] = atom_w1; wp.p[1] = atom_w2; wp.p[2] = bond_w1;
    wp.p[3] = bond_w2; wp.p[4] = conv_w1; wp.p[5] = conv_w2;

    auto WT = [&](int i) { return pw16 + (size_t)i * D * D; };
    dim3 gN(D / BN, (N + BM - 1) / BM);
    dim3 gB(D / BN, (NBOND + BM - 1) / BM);

    int emb4 = 9 * 128 * D / 4;

    // launches 0-4
    transpose_all_kernel<<<dim3(D / 32, D / 32, 12), dim3(32, 8)>>>(wp, pw16);        // 0
    zero2_kernel<<<(N + 255) / 256, 256>>>(phist, pcnt, N);                            // 1
    cvt_emb_kernel<<<(emb4 + 255) / 256, 256>>>((const float4*)atom_emb, (__half2*)paemb, emb4); // 2
    embed_ln_atom_kernel<<<N, 192>>>(x, paemb, atom_ln_g, atom_ln_b, pa16);            // 3
    embed_ln_bond_kernel<<<NBOND, 256>>>(bond_emb, bond_ln_g, bond_ln_b, pbtmp);       // 4
    // launch 5: full N-GEMM -> ncu
    gemm_kernel<2, true ><<<gN, GEMM_THREADS, GEMM_SMEM>>>(pa16, WT(0), atom_b1, pt16, N, nullptr);   // 5
    // atom GEMM2 writes fp32 h AND fp16 mirror (seed fused)
    gemm_kernel<0, false><<<gN, GEMM_THREADS, GEMM_SMEM>>>(pt16, WT(1), atom_b2, phA, N, ph16);

    // CSR build
    hist_kernel<<<(E + 255) / 256, 256>>>(edge_index, phist, E);
    scan_kernel<<<1, 1024>>>(phist, prow, N);
    scatter_kernel<<<(E + 255) / 256, 256>>>(edge_index, edge_attr, prow, pcnt, psrcs, pcodes, E);

    // bond-table encoder GEMMs (512 rows)
    gemm_kernel<2, true ><<<gB, GEMM_THREADS, GEMM_SMEM>>>(pbtmp, WT(2), bond_b1, pbtmp + (size_t)NBOND * D, NBOND, nullptr);
    gemm_kernel<0, true ><<<gB, GEMM_THREADS, GEMM_SMEM>>>(pbtmp + (size_t)NBOND * D, WT(3), bond_b2, petab, NBOND, nullptr);

    const float* hcur = phA;
    float* hnext = phB;
    for (int l = 0; l < N_LAYERS; l++) {
        // a16[n] = fp16( h16[n] + sum_{edges->n} relu(h16[src] + etab[code]) )
        edge_agg_kernel<<<N, 192>>>(prow, psrcs, pcodes, ph16, petab, pa16);
        // conv MLP
        gemm_kernel<1, true ><<<gN, GEMM_THREADS, GEMM_SMEM>>>(pa16, WT(4 + l), conv_b1 + l * D, pt16, N, nullptr);
        gemm_kernel<0, false><<<gN, GEMM_THREADS, GEMM_SMEM>>>(pt16, WT(8 + l), conv_b2 + l * D, pz, N, nullptr);
        // h = LN(gelu(z) + h_in); refresh h16 mirror (except last layer)
        float*  dst = (l == N_LAYERS - 1) ? out : hnext;
        __half* mir = (l == N_LAYERS - 1) ? nullptr : ph16;
        ln_res_kernel<<<N, 256>>>(pz, hcur, ln_g + l * D, ln_b + l * D, dst, mir);

        float* old = (float*)hcur;
        hcur = dst;
        hnext = old;
    }
}